// round 12
// baseline (speedup 1.0000x reference)
#include <cuda_runtime.h>

#define CN0 50000
#define CN1 150000
#define CN2 20000
#define CN3 5000
#define CN4 1000
#define CE0 800000
#define CE1 1500000
#define CNNZ 300000
#define DD 64

// ---------------- scratch (static device globals; no allocation) ----------------
__device__ float g_m0[CN0 * DD];
__device__ float g_m1[CN1 * DD];
__device__ float g_ms[CN1 * DD];
__device__ float g_mt[CN0 * DD];
__device__ float g_accA0[CN0 * DD];
__device__ float g_accB0[CN0 * DD];
__device__ float g_accA1[CN1 * DD];
__device__ float g_accB1[CN1 * DD];
__device__ int4  g_e0[CE0];    // packed {src, dst, coeff_bits, 0}
__device__ int4  g_e1[CE1];
__device__ int4  g_ei[CNNZ];   // packed {row, col, val_bits, 0}

// ---------------- packed f32x2 helpers (Blackwell FFMA2) ----------------
__device__ __forceinline__ unsigned long long pack2(float x, float y) {
    unsigned long long r;
    asm("mov.b64 %0, {%1,%2};" : "=l"(r) : "f"(x), "f"(y));
    return r;
}
__device__ __forceinline__ void fma2(unsigned long long& d, unsigned long long a,
                                     unsigned long long b) {
    asm("fma.rn.f32x2 %0, %1, %2, %0;" : "+l"(d) : "l"(a), "l"(b));
}
__device__ __forceinline__ float2 unpack2(unsigned long long v) {
    float2 f;
    asm("mov.b64 {%0,%1}, %2;" : "=f"(f.x), "=f"(f.y) : "l"(v));
    return f;
}

// =====================================================================
// Dual GEMM: out1 = X@W1, out2 = X@W2.  128 rows/block, 256 threads.
// =====================================================================
__global__ __launch_bounds__(256) void gemm64_dual(const float* __restrict__ X,
                                                   const float* __restrict__ W1,
                                                   const float* __restrict__ W2,
                                                   float* __restrict__ out1,
                                                   float* __restrict__ out2, int N) {
    __shared__ __align__(16) float sW1[64 * 64];
    __shared__ __align__(16) float sW2[64 * 64];
    __shared__ __align__(16) float sXT[128 * 64];
    int tid = threadIdx.x;
#pragma unroll
    for (int i = 0; i < 16; i++) {
        sW1[tid + i * 256] = W1[tid + i * 256];
        sW2[tid + i * 256] = W2[tid + i * 256];
    }
    long r0 = (long)blockIdx.x * 128;
#pragma unroll
    for (int i = 0; i < 32; i++) {
        int li = tid + i * 256;
        int row = li >> 6, col = li & 63;
        long gr = r0 + row;
        float v = (gr < N) ? X[gr * 64 + col] : 0.f;
        sXT[col * 128 + (((row >> 2) ^ (col & 31)) << 2) + (row & 3)] = v;
    }
    __syncthreads();

    int tx = tid & 15, ty = tid >> 4;
    unsigned long long a1[8][2], a2[8][2];
#pragma unroll
    for (int r = 0; r < 8; r++) { a1[r][0] = a1[r][1] = a2[r][0] = a2[r][1] = 0ull; }

    const float4* sXT4 = (const float4*)sXT;
    const ulonglong2* sW1v = (const ulonglong2*)sW1;
    const ulonglong2* sW2v = (const ulonglong2*)sW2;
    int g0 = 2 * ty, g1 = 2 * ty + 1;
#pragma unroll 8
    for (int k = 0; k < 64; k++) {
        float4 xa = sXT4[k * 32 + (g0 ^ (k & 31))];
        float4 xb = sXT4[k * 32 + (g1 ^ (k & 31))];
        ulonglong2 w1 = sW1v[k * 16 + tx];
        ulonglong2 w2 = sW2v[k * 16 + tx];
        float xs[8] = {xa.x, xa.y, xa.z, xa.w, xb.x, xb.y, xb.z, xb.w};
#pragma unroll
        for (int r = 0; r < 8; r++) {
            unsigned long long xx = pack2(xs[r], xs[r]);
            fma2(a1[r][0], xx, w1.x); fma2(a1[r][1], xx, w1.y);
            fma2(a2[r][0], xx, w2.x); fma2(a2[r][1], xx, w2.y);
        }
    }
#pragma unroll
    for (int r = 0; r < 8; r++) {
        long row = r0 + ty * 8 + r;
        if (row < N) {
            float2 lo = unpack2(a1[r][0]), hi = unpack2(a1[r][1]);
            ((float4*)out1)[row * 16 + tx] = make_float4(lo.x, lo.y, hi.x, hi.y);
            lo = unpack2(a2[r][0]); hi = unpack2(a2[r][1]);
            ((float4*)out2)[row * 16 + tx] = make_float4(lo.x, lo.y, hi.x, hi.y);
        }
    }
}

// =====================================================================
// Fused epilogue: out = relu((relu(A)+relu(B)) @ W)
// =====================================================================
__global__ __launch_bounds__(256) void gemm64_fused(const float* __restrict__ A,
                                                    const float* __restrict__ B,
                                                    const float* __restrict__ W,
                                                    float* __restrict__ out, int N) {
    __shared__ __align__(16) float sW[64 * 64];
    __shared__ __align__(16) float sXT[128 * 64];
    int tid = threadIdx.x;
#pragma unroll
    for (int i = 0; i < 16; i++) sW[tid + i * 256] = W[tid + i * 256];
    long r0 = (long)blockIdx.x * 128;
#pragma unroll
    for (int i = 0; i < 32; i++) {
        int li = tid + i * 256;
        int row = li >> 6, col = li & 63;
        long gr = r0 + row;
        float v = 0.f;
        if (gr < N) {
            long idx = gr * 64 + col;
            v = fmaxf(A[idx], 0.f) + fmaxf(B[idx], 0.f);
        }
        sXT[col * 128 + (((row >> 2) ^ (col & 31)) << 2) + (row & 3)] = v;
    }
    __syncthreads();

    int tx = tid & 15, ty = tid >> 4;
    unsigned long long a1[8][2];
#pragma unroll
    for (int r = 0; r < 8; r++) { a1[r][0] = a1[r][1] = 0ull; }

    const float4* sXT4 = (const float4*)sXT;
    const ulonglong2* sWv = (const ulonglong2*)sW;
    int g0 = 2 * ty, g1 = 2 * ty + 1;
#pragma unroll 8
    for (int k = 0; k < 64; k++) {
        float4 xa = sXT4[k * 32 + (g0 ^ (k & 31))];
        float4 xb = sXT4[k * 32 + (g1 ^ (k & 31))];
        ulonglong2 w = sWv[k * 16 + tx];
        float xs[8] = {xa.x, xa.y, xa.z, xa.w, xb.x, xb.y, xb.z, xb.w};
#pragma unroll
        for (int r = 0; r < 8; r++) {
            unsigned long long xx = pack2(xs[r], xs[r]);
            fma2(a1[r][0], xx, w.x); fma2(a1[r][1], xx, w.y);
        }
    }
#pragma unroll
    for (int r = 0; r < 8; r++) {
        long row = r0 + ty * 8 + r;
        if (row < N) {
            float2 lo = unpack2(a1[r][0]), hi = unpack2(a1[r][1]);
            ((float4*)out)[row * 16 + tx] =
                make_float4(fmaxf(lo.x, 0.f), fmaxf(lo.y, 0.f),
                            fmaxf(hi.x, 0.f), fmaxf(hi.y, 0.f));
        }
    }
}

// =====================================================================
// Prologue: pack adjacency metadata {src, dst, coeff} -> int4 buffer.
// coeff = val * (cci . a).  Independent of gemms -> fully overlapped.
// =====================================================================
__global__ __launch_bounds__(256) void pack_adj(const int* __restrict__ src,
                                                const int* __restrict__ dst,
                                                const float* __restrict__ val,
                                                const float* __restrict__ cci,
                                                const float* __restrict__ a,
                                                int4* __restrict__ out, int E) {
    int e = blockIdx.x * blockDim.x + threadIdx.x;
    if (e >= E) return;
    float c = val[e] * (cci[e * 3 + 0] * a[0] + cci[e * 3 + 1] * a[1] +
                        cci[e * 3 + 2] * a[2]);
    out[e] = make_int4(src[e], dst[e], __float_as_int(c), 0);
}

__global__ __launch_bounds__(256) void pack_inc(const int* __restrict__ row,
                                                const int* __restrict__ col,
                                                const float* __restrict__ val,
                                                int4* __restrict__ out, int E) {
    int e = blockIdx.x * blockDim.x + threadIdx.x;
    if (e >= E) return;
    out[e] = make_int4(row[e], col[e], __float_as_int(val[e]), 0);
}

// =====================================================================
// Packed adjacency scatter, ILP-2.  Per warp per 2 edges:
//   1x LDG.128 meta (2 addrs/warp) + 1x LDG.128 gather + 1x RED.v4
// vs 8 LSU instructions before.  E divisible by 32 (all are).
// =====================================================================
__global__ __launch_bounds__(256) void scatter_packed2(const int4* __restrict__ eb,
                                                       const float* __restrict__ m,
                                                       float* __restrict__ acc) {
    int base = blockIdx.x * 32;
    int tid = threadIdx.x;
    int le = tid >> 4, sub = tid & 15;
    int4 ma = eb[base + le];
    int4 mb = eb[base + 16 + le];

    float4 v0 = reinterpret_cast<const float4*>(m + (long)ma.x * 64)[sub];
    float4 v1 = reinterpret_cast<const float4*>(m + (long)mb.x * 64)[sub];
    float c0 = __int_as_float(ma.z), c1 = __int_as_float(mb.z);
    v0.x *= c0; v0.y *= c0; v0.z *= c0; v0.w *= c0;
    v1.x *= c1; v1.y *= c1; v1.z *= c1; v1.w *= c1;

    float* p0 = acc + (long)ma.y * 64 + sub * 4;
    float* p1 = acc + (long)mb.y * 64 + sub * 4;
    asm volatile("red.global.add.v4.f32 [%0], {%1,%2,%3,%4};"
                 :: "l"(p0), "f"(v0.x), "f"(v0.y), "f"(v0.z), "f"(v0.w) : "memory");
    asm volatile("red.global.add.v4.f32 [%0], {%1,%2,%3,%4};"
                 :: "l"(p1), "f"(v1.x), "f"(v1.y), "f"(v1.z), "f"(v1.w) : "memory");
}

// =====================================================================
// Packed incidence scatter, ILP-2 edges x 2 directions.
// =====================================================================
__global__ __launch_bounds__(256) void scatter_inc_packed2(const int4* __restrict__ eb,
                                                           const float* __restrict__ ms,
                                                           const float* __restrict__ mt,
                                                           float* __restrict__ accB0,
                                                           float* __restrict__ accB1) {
    int base = blockIdx.x * 32;
    int tid = threadIdx.x;
    int le = tid >> 4, sub = tid & 15;
    int4 ma = eb[base + le];
    int4 mb = eb[base + 16 + le];
    float v0 = __int_as_float(ma.z), v1 = __int_as_float(mb.z);

    float4 a0 = reinterpret_cast<const float4*>(ms + (long)ma.y * 64)[sub];
    float4 a1 = reinterpret_cast<const float4*>(ms + (long)mb.y * 64)[sub];
    float4 b0 = reinterpret_cast<const float4*>(mt + (long)ma.x * 64)[sub];
    float4 b1 = reinterpret_cast<const float4*>(mt + (long)mb.x * 64)[sub];

    a0.x *= v0; a0.y *= v0; a0.z *= v0; a0.w *= v0;
    a1.x *= v1; a1.y *= v1; a1.z *= v1; a1.w *= v1;
    b0.x *= v0; b0.y *= v0; b0.z *= v0; b0.w *= v0;
    b1.x *= v1; b1.y *= v1; b1.z *= v1; b1.w *= v1;

    float* pa0 = accB0 + (long)ma.x * 64 + sub * 4;
    float* pa1 = accB0 + (long)mb.x * 64 + sub * 4;
    float* pb0 = accB1 + (long)ma.y * 64 + sub * 4;
    float* pb1 = accB1 + (long)mb.y * 64 + sub * 4;
    asm volatile("red.global.add.v4.f32 [%0], {%1,%2,%3,%4};"
                 :: "l"(pa0), "f"(a0.x), "f"(a0.y), "f"(a0.z), "f"(a0.w) : "memory");
    asm volatile("red.global.add.v4.f32 [%0], {%1,%2,%3,%4};"
                 :: "l"(pa1), "f"(a1.x), "f"(a1.y), "f"(a1.z), "f"(a1.w) : "memory");
    asm volatile("red.global.add.v4.f32 [%0], {%1,%2,%3,%4};"
                 :: "l"(pb0), "f"(b0.x), "f"(b0.y), "f"(b0.z), "f"(b0.w) : "memory");
    asm volatile("red.global.add.v4.f32 [%0], {%1,%2,%3,%4};"
                 :: "l"(pb1), "f"(b1.x), "f"(b1.y), "f"(b1.z), "f"(b1.w) : "memory");
}

// ---------------- stream/event pool: LAZY init on first kernel_launch ----------------
static cudaStream_t s1 = 0, s2 = 0, s3 = 0;
static cudaEvent_t eRoot = 0, eZ1 = 0, eZ = 0, eG0 = 0, eG1 = 0, eI = 0, eF0 = 0, eP1 = 0;
static int g_init_state = 0;  // 0 = untried, 1 = ok, -1 = failed (serial fallback)

static void ensure_init() {
    if (g_init_state != 0) return;
    bool ok = true;
    ok &= (cudaStreamCreateWithFlags(&s1, cudaStreamNonBlocking) == cudaSuccess);
    ok &= (cudaStreamCreateWithFlags(&s2, cudaStreamNonBlocking) == cudaSuccess);
    ok &= (cudaStreamCreateWithFlags(&s3, cudaStreamNonBlocking) == cudaSuccess);
    ok &= (cudaEventCreateWithFlags(&eRoot, cudaEventDisableTiming) == cudaSuccess);
    ok &= (cudaEventCreateWithFlags(&eZ1, cudaEventDisableTiming) == cudaSuccess);
    ok &= (cudaEventCreateWithFlags(&eZ, cudaEventDisableTiming) == cudaSuccess);
    ok &= (cudaEventCreateWithFlags(&eG0, cudaEventDisableTiming) == cudaSuccess);
    ok &= (cudaEventCreateWithFlags(&eI, cudaEventDisableTiming) == cudaSuccess);
    ok &= (cudaEventCreateWithFlags(&eF0, cudaEventDisableTiming) == cudaSuccess);
    ok &= (cudaEventCreateWithFlags(&eP1, cudaEventDisableTiming) == cudaSuccess);
    ok &= (cudaEventCreateWithFlags(&eG1, cudaEventDisableTiming) == cudaSuccess);
    g_init_state = ok ? 1 : -1;
}

// ---------------- launch ----------------
extern "C" void kernel_launch(void* const* d_in, const int* in_sizes, int n_in,
                              void* d_out, int out_size) {
    ensure_init();

    const float* x0   = (const float*)d_in[0];
    const float* x1   = (const float*)d_in[1];
    const float* x2   = (const float*)d_in[2];
    const float* x3   = (const float*)d_in[3];
    const float* x4   = (const float*)d_in[4];
    const int*   adj0 = (const int*)d_in[5];
    const float* adj0v= (const float*)d_in[6];
    const int*   adj1 = (const int*)d_in[7];
    const float* adj1v= (const float*)d_in[8];
    const int*   inc  = (const int*)d_in[9];
    const float* incv = (const float*)d_in[10];
    const float* cci0 = (const float*)d_in[11];
    const float* cci1 = (const float*)d_in[12];
    const float* Whbs0= (const float*)d_in[13];
    const float* ahbs0= (const float*)d_in[14];
    const float* Whbs1= (const float*)d_in[15];
    const float* ahbs1= (const float*)d_in[16];
    const float* Ws   = (const float*)d_in[17];
    const float* Wt   = (const float*)d_in[18];
    const float* Wag0 = (const float*)d_in[19];
    const float* Wag1 = (const float*)d_in[20];
    float* out = (float*)d_out;

    float *pm0, *pm1, *pms, *pmt, *pA0, *pB0, *pA1, *pB1;
    int4 *pe0, *pe1, *pei;
    cudaGetSymbolAddress((void**)&pm0, g_m0);
    cudaGetSymbolAddress((void**)&pm1, g_m1);
    cudaGetSymbolAddress((void**)&pms, g_ms);
    cudaGetSymbolAddress((void**)&pmt, g_mt);
    cudaGetSymbolAddress((void**)&pA0, g_accA0);
    cudaGetSymbolAddress((void**)&pB0, g_accB0);
    cudaGetSymbolAddress((void**)&pA1, g_accA1);
    cudaGetSymbolAddress((void**)&pB1, g_accB1);
    cudaGetSymbolAddress((void**)&pe0, g_e0);
    cudaGetSymbolAddress((void**)&pe1, g_e1);
    cudaGetSymbolAddress((void**)&pei, g_ei);

    if (g_init_state == 1) {
        // ======== multi-stream overlapped schedule ========
        cudaEventRecord(eRoot, 0);
        cudaStreamWaitEvent(s1, eRoot, 0);
        cudaStreamWaitEvent(s2, eRoot, 0);
        cudaStreamWaitEvent(s3, eRoot, 0);

        // s2: zero accumulators (A1/B1 first) then pack E0 metadata
        cudaMemsetAsync(pA1, 0, sizeof(float) * (size_t)CN1 * DD, s2);
        cudaMemsetAsync(pB1, 0, sizeof(float) * (size_t)CN1 * DD, s2);
        cudaEventRecord(eZ1, s2);
        cudaMemsetAsync(pA0, 0, sizeof(float) * (size_t)CN0 * DD, s2);
        cudaMemsetAsync(pB0, 0, sizeof(float) * (size_t)CN0 * DD, s2);
        pack_adj<<<(CE0 + 255) / 256, 256, 0, s2>>>(adj0, adj0 + CE0, adj0v, cci0,
                                                    ahbs0, pe0, CE0);
        cudaEventRecord(eZ, s2);   // zeros + pack0 done

        // s1: chain0 — gemm(x0)
        gemm64_dual<<<(CN0 + 127) / 128, 256, 0, s1>>>(x0, Whbs0, Wt, pm0, pmt, CN0);
        cudaEventRecord(eG0, s1);

        // main: chain1 — gemm(x1)
        gemm64_dual<<<(CN1 + 127) / 128, 256, 0, 0>>>(x1, Whbs1, Ws, pm1, pms, CN1);
        cudaEventRecord(eG1, 0);

        // s3: pack E1 + inc metadata, pass-through copies, then scatter_inc
        pack_adj<<<(CE1 + 255) / 256, 256, 0, s3>>>(adj1, adj1 + CE1, adj1v, cci1,
                                                    ahbs1, pe1, CE1);
        cudaEventRecord(eP1, s3);
        pack_inc<<<(CNNZ + 255) / 256, 256, 0, s3>>>(inc, inc + CNNZ, incv, pei, CNNZ);
        cudaMemcpyAsync(out + (long)(CN0 + CN1) * DD, x2, sizeof(float) * (size_t)CN2 * DD,
                        cudaMemcpyDeviceToDevice, s3);
        cudaMemcpyAsync(out + (long)(CN0 + CN1 + CN2) * DD, x3, sizeof(float) * (size_t)CN3 * DD,
                        cudaMemcpyDeviceToDevice, s3);
        cudaMemcpyAsync(out + (long)(CN0 + CN1 + CN2 + CN3) * DD, x4,
                        sizeof(float) * (size_t)CN4 * DD, cudaMemcpyDeviceToDevice, s3);
        cudaStreamWaitEvent(s3, eG0, 0);
        cudaStreamWaitEvent(s3, eG1, 0);
        cudaStreamWaitEvent(s3, eZ, 0);
        scatter_inc_packed2<<<CNNZ / 32, 256, 0, s3>>>(pei, pms, pmt, pB0, pB1);
        cudaEventRecord(eI, s3);

        // s1: scatter0 (needs gemm0 in-stream + eZ which covers pack0+zeros) then fused0
        cudaStreamWaitEvent(s1, eZ, 0);
        scatter_packed2<<<CE0 / 32, 256, 0, s1>>>(pe0, pm0, pA0);
        cudaStreamWaitEvent(s1, eI, 0);
        gemm64_fused<<<(CN0 + 127) / 128, 256, 0, s1>>>(pA0, pB0, Wag0, out, CN0);
        cudaEventRecord(eF0, s1);

        // main: scatter1 (needs gemm1 in-stream + zeros A1/B1 + pack1) then fused1
        cudaStreamWaitEvent(0, eZ1, 0);
        cudaStreamWaitEvent(0, eP1, 0);
        scatter_packed2<<<CE1 / 32, 256, 0, 0>>>(pe1, pm1, pA1);
        cudaStreamWaitEvent(0, eI, 0);
        gemm64_fused<<<(CN1 + 127) / 128, 256, 0, 0>>>(pA1, pB1, Wag1,
                                                       out + (long)CN0 * DD, CN1);
        cudaStreamWaitEvent(0, eF0, 0);  // join s1 (s2/s3 ordered via eZ/eZ1/eI)
    } else {
        // ======== serial fallback ========
        cudaMemsetAsync(pA0, 0, sizeof(float) * (size_t)CN0 * DD);
        cudaMemsetAsync(pB0, 0, sizeof(float) * (size_t)CN0 * DD);
        cudaMemsetAsync(pA1, 0, sizeof(float) * (size_t)CN1 * DD);
        cudaMemsetAsync(pB1, 0, sizeof(float) * (size_t)CN1 * DD);
        pack_adj<<<(CE0 + 255) / 256, 256>>>(adj0, adj0 + CE0, adj0v, cci0, ahbs0, pe0, CE0);
        pack_adj<<<(CE1 + 255) / 256, 256>>>(adj1, adj1 + CE1, adj1v, cci1, ahbs1, pe1, CE1);
        pack_inc<<<(CNNZ + 255) / 256, 256>>>(inc, inc + CNNZ, incv, pei, CNNZ);
        gemm64_dual<<<(CN0 + 127) / 128, 256>>>(x0, Whbs0, Wt, pm0, pmt, CN0);
        gemm64_dual<<<(CN1 + 127) / 128, 256>>>(x1, Whbs1, Ws, pm1, pms, CN1);
        scatter_packed2<<<CE0 / 32, 256>>>(pe0, pm0, pA0);
        scatter_packed2<<<CE1 / 32, 256>>>(pe1, pm1, pA1);
        scatter_inc_packed2<<<CNNZ / 32, 256>>>(pei, pms, pmt, pB0, pB1);
        gemm64_fused<<<(CN0 + 127) / 128, 256>>>(pA0, pB0, Wag0, out, CN0);
        gemm64_fused<<<(CN1 + 127) / 128, 256>>>(pA1, pB1, Wag1, out + (long)CN0 * DD, CN1);
        cudaMemcpyAsync(out + (long)(CN0 + CN1) * DD, x2, sizeof(float) * (size_t)CN2 * DD,
                        cudaMemcpyDeviceToDevice);
        cudaMemcpyAsync(out + (long)(CN0 + CN1 + CN2) * DD, x3, sizeof(float) * (size_t)CN3 * DD,
                        cudaMemcpyDeviceToDevice);
        cudaMemcpyAsync(out + (long)(CN0 + CN1 + CN2 + CN3) * DD, x4,
                        sizeof(float) * (size_t)CN4 * DD, cudaMemcpyDeviceToDevice);
    }
}

// round 13
// speedup vs baseline: 1.0671x; 1.0671x over previous
#include <cuda_runtime.h>

#define CN0 50000
#define CN1 150000
#define CN2 20000
#define CN3 5000
#define CN4 1000
#define CE0 800000
#define CE1 1500000
#define CNNZ 300000
#define DD 64

// ---------------- scratch (static device globals; no allocation) ----------------
__device__ float g_m0[CN0 * DD];
__device__ float g_m1[CN1 * DD];
__device__ float g_ms[CN1 * DD];
__device__ float g_mt[CN0 * DD];
__device__ float g_accA0[CN0 * DD];
__device__ float g_accB0[CN0 * DD];
__device__ float g_accA1[CN1 * DD];
__device__ float g_accB1[CN1 * DD];
// CSR scratch
__device__ int  g_deg0[CN0], g_off0[CN0], g_cur0[CN0];
__device__ int  g_deg1[CN1], g_off1[CN1], g_cur1[CN1];
__device__ int2 g_csr0[CE0];   // {src, coeff_bits} sorted by dst
__device__ int2 g_csr1[CE1];
__device__ int  g_bsum[256];   // scan partials (reused sequentially)

// ---------------- packed f32x2 helpers (Blackwell FFMA2) ----------------
__device__ __forceinline__ unsigned long long pack2(float x, float y) {
    unsigned long long r;
    asm("mov.b64 %0, {%1,%2};" : "=l"(r) : "f"(x), "f"(y));
    return r;
}
__device__ __forceinline__ void fma2(unsigned long long& d, unsigned long long a,
                                     unsigned long long b) {
    asm("fma.rn.f32x2 %0, %1, %2, %0;" : "+l"(d) : "l"(a), "l"(b));
}
__device__ __forceinline__ float2 unpack2(unsigned long long v) {
    float2 f;
    asm("mov.b64 {%0,%1}, %2;" : "=f"(f.x), "=f"(f.y) : "l"(v));
    return f;
}

// =====================================================================
// Dual GEMM: out1 = X@W1, out2 = X@W2.  128 rows/block, 256 threads.
// =====================================================================
__global__ __launch_bounds__(256) void gemm64_dual(const float* __restrict__ X,
                                                   const float* __restrict__ W1,
                                                   const float* __restrict__ W2,
                                                   float* __restrict__ out1,
                                                   float* __restrict__ out2, int N) {
    __shared__ __align__(16) float sW1[64 * 64];
    __shared__ __align__(16) float sW2[64 * 64];
    __shared__ __align__(16) float sXT[128 * 64];
    int tid = threadIdx.x;
#pragma unroll
    for (int i = 0; i < 16; i++) {
        sW1[tid + i * 256] = W1[tid + i * 256];
        sW2[tid + i * 256] = W2[tid + i * 256];
    }
    long r0 = (long)blockIdx.x * 128;
#pragma unroll
    for (int i = 0; i < 32; i++) {
        int li = tid + i * 256;
        int row = li >> 6, col = li & 63;
        long gr = r0 + row;
        float v = (gr < N) ? X[gr * 64 + col] : 0.f;
        sXT[col * 128 + (((row >> 2) ^ (col & 31)) << 2) + (row & 3)] = v;
    }
    __syncthreads();

    int tx = tid & 15, ty = tid >> 4;
    unsigned long long a1[8][2], a2[8][2];
#pragma unroll
    for (int r = 0; r < 8; r++) { a1[r][0] = a1[r][1] = a2[r][0] = a2[r][1] = 0ull; }

    const float4* sXT4 = (const float4*)sXT;
    const ulonglong2* sW1v = (const ulonglong2*)sW1;
    const ulonglong2* sW2v = (const ulonglong2*)sW2;
    int g0 = 2 * ty, g1 = 2 * ty + 1;
#pragma unroll 8
    for (int k = 0; k < 64; k++) {
        float4 xa = sXT4[k * 32 + (g0 ^ (k & 31))];
        float4 xb = sXT4[k * 32 + (g1 ^ (k & 31))];
        ulonglong2 w1 = sW1v[k * 16 + tx];
        ulonglong2 w2 = sW2v[k * 16 + tx];
        float xs[8] = {xa.x, xa.y, xa.z, xa.w, xb.x, xb.y, xb.z, xb.w};
#pragma unroll
        for (int r = 0; r < 8; r++) {
            unsigned long long xx = pack2(xs[r], xs[r]);
            fma2(a1[r][0], xx, w1.x); fma2(a1[r][1], xx, w1.y);
            fma2(a2[r][0], xx, w2.x); fma2(a2[r][1], xx, w2.y);
        }
    }
#pragma unroll
    for (int r = 0; r < 8; r++) {
        long row = r0 + ty * 8 + r;
        if (row < N) {
            float2 lo = unpack2(a1[r][0]), hi = unpack2(a1[r][1]);
            ((float4*)out1)[row * 16 + tx] = make_float4(lo.x, lo.y, hi.x, hi.y);
            lo = unpack2(a2[r][0]); hi = unpack2(a2[r][1]);
            ((float4*)out2)[row * 16 + tx] = make_float4(lo.x, lo.y, hi.x, hi.y);
        }
    }
}

// =====================================================================
// Fused epilogue: out = relu((relu(A)+relu(B)) @ W)
// =====================================================================
__global__ __launch_bounds__(256) void gemm64_fused(const float* __restrict__ A,
                                                    const float* __restrict__ B,
                                                    const float* __restrict__ W,
                                                    float* __restrict__ out, int N) {
    __shared__ __align__(16) float sW[64 * 64];
    __shared__ __align__(16) float sXT[128 * 64];
    int tid = threadIdx.x;
#pragma unroll
    for (int i = 0; i < 16; i++) sW[tid + i * 256] = W[tid + i * 256];
    long r0 = (long)blockIdx.x * 128;
#pragma unroll
    for (int i = 0; i < 32; i++) {
        int li = tid + i * 256;
        int row = li >> 6, col = li & 63;
        long gr = r0 + row;
        float v = 0.f;
        if (gr < N) {
            long idx = gr * 64 + col;
            v = fmaxf(A[idx], 0.f) + fmaxf(B[idx], 0.f);
        }
        sXT[col * 128 + (((row >> 2) ^ (col & 31)) << 2) + (row & 3)] = v;
    }
    __syncthreads();

    int tx = tid & 15, ty = tid >> 4;
    unsigned long long a1[8][2];
#pragma unroll
    for (int r = 0; r < 8; r++) { a1[r][0] = a1[r][1] = 0ull; }

    const float4* sXT4 = (const float4*)sXT;
    const ulonglong2* sWv = (const ulonglong2*)sW;
    int g0 = 2 * ty, g1 = 2 * ty + 1;
#pragma unroll 8
    for (int k = 0; k < 64; k++) {
        float4 xa = sXT4[k * 32 + (g0 ^ (k & 31))];
        float4 xb = sXT4[k * 32 + (g1 ^ (k & 31))];
        ulonglong2 w = sWv[k * 16 + tx];
        float xs[8] = {xa.x, xa.y, xa.z, xa.w, xb.x, xb.y, xb.z, xb.w};
#pragma unroll
        for (int r = 0; r < 8; r++) {
            unsigned long long xx = pack2(xs[r], xs[r]);
            fma2(a1[r][0], xx, w.x); fma2(a1[r][1], xx, w.y);
        }
    }
#pragma unroll
    for (int r = 0; r < 8; r++) {
        long row = r0 + ty * 8 + r;
        if (row < N) {
            float2 lo = unpack2(a1[r][0]), hi = unpack2(a1[r][1]);
            ((float4*)out)[row * 16 + tx] =
                make_float4(fmaxf(lo.x, 0.f), fmaxf(lo.y, 0.f),
                            fmaxf(hi.x, 0.f), fmaxf(hi.y, 0.f));
        }
    }
}

// ======================= CSR build kernels =======================
__global__ __launch_bounds__(256) void hist_kernel(const int* __restrict__ dst,
                                                   int* __restrict__ deg, int E) {
    int e = blockIdx.x * blockDim.x + threadIdx.x;
    if (e < E) atomicAdd(&deg[dst[e]], 1);
}

// per-1024-block exclusive scan; writes block totals
__global__ __launch_bounds__(1024) void scan_block(const int* __restrict__ in,
                                                   int* __restrict__ out,
                                                   int* __restrict__ bsum, int N) {
    __shared__ int s[1024];
    int gid = blockIdx.x * 1024 + threadIdx.x;
    int v = (gid < N) ? in[gid] : 0;
    s[threadIdx.x] = v;
    __syncthreads();
#pragma unroll
    for (int d = 1; d < 1024; d <<= 1) {
        int t = (threadIdx.x >= d) ? s[threadIdx.x - d] : 0;
        __syncthreads();
        s[threadIdx.x] += t;
        __syncthreads();
    }
    if (gid < N) out[gid] = s[threadIdx.x] - v;  // exclusive
    if (threadIdx.x == 1023) bsum[blockIdx.x] = s[1023];
}

// single-block scan of <=256 block totals -> exclusive offsets
__global__ __launch_bounds__(256) void scan_top(int* __restrict__ bsum, int nb) {
    __shared__ int s[256];
    int v = (threadIdx.x < nb) ? bsum[threadIdx.x] : 0;
    s[threadIdx.x] = v;
    __syncthreads();
#pragma unroll
    for (int d = 1; d < 256; d <<= 1) {
        int t = (threadIdx.x >= d) ? s[threadIdx.x - d] : 0;
        __syncthreads();
        s[threadIdx.x] += t;
        __syncthreads();
    }
    if (threadIdx.x < nb) bsum[threadIdx.x] = s[threadIdx.x] - v;
}

__global__ __launch_bounds__(256) void scan_add(int* __restrict__ off,
                                                const int* __restrict__ bsum,
                                                int* __restrict__ cur, int N) {
    int gid = blockIdx.x * blockDim.x + threadIdx.x;
    if (gid < N) {
        int o = off[gid] + bsum[gid >> 10];
        off[gid] = o;
        cur[gid] = o;
    }
}

// reorder edges into CSR order; coeff = val * (cci . a) folded in
__global__ __launch_bounds__(256) void reorder_adj(const int* __restrict__ src,
                                                   const int* __restrict__ dst,
                                                   const float* __restrict__ val,
                                                   const float* __restrict__ cci,
                                                   const float* __restrict__ a,
                                                   int* __restrict__ cur,
                                                   int2* __restrict__ csr, int E) {
    int e = blockIdx.x * blockDim.x + threadIdx.x;
    if (e >= E) return;
    float c = val[e] * (cci[e * 3 + 0] * a[0] + cci[e * 3 + 1] * a[1] +
                        cci[e * 3 + 2] * a[2]);
    int pos = atomicAdd(&cur[dst[e]], 1);
    csr[pos] = make_int2(src[e], __float_as_int(c));
}

// =====================================================================
// CSR gather-side segment sum: 16 lanes per node, register accumulator,
// single STG.128 per node.  No atomics, no accumulator memset needed.
// N divisible by 16 (50000, 150000 both are).
// =====================================================================
__global__ __launch_bounds__(256) void csr_accum(const int* __restrict__ off,
                                                 const int* __restrict__ deg,
                                                 const int2* __restrict__ csr,
                                                 const float* __restrict__ m,
                                                 float* __restrict__ acc, int N) {
    int tid = threadIdx.x;
    int node = blockIdx.x * 16 + (tid >> 4);
    int sub = tid & 15;
    int start = off[node];
    int d = deg[node];
    float4 s = make_float4(0.f, 0.f, 0.f, 0.f);
    int j = 0;
    for (; j + 2 <= d; j += 2) {
        int2 e0 = csr[start + j];
        int2 e1 = csr[start + j + 1];
        float4 v0 = reinterpret_cast<const float4*>(m + (long)e0.x * 64)[sub];
        float4 v1 = reinterpret_cast<const float4*>(m + (long)e1.x * 64)[sub];
        float c0 = __int_as_float(e0.y), c1 = __int_as_float(e1.y);
        s.x = fmaf(c0, v0.x, s.x); s.y = fmaf(c0, v0.y, s.y);
        s.z = fmaf(c0, v0.z, s.z); s.w = fmaf(c0, v0.w, s.w);
        s.x = fmaf(c1, v1.x, s.x); s.y = fmaf(c1, v1.y, s.y);
        s.z = fmaf(c1, v1.z, s.z); s.w = fmaf(c1, v1.w, s.w);
    }
    if (j < d) {
        int2 e0 = csr[start + j];
        float4 v0 = reinterpret_cast<const float4*>(m + (long)e0.x * 64)[sub];
        float c0 = __int_as_float(e0.y);
        s.x = fmaf(c0, v0.x, s.x); s.y = fmaf(c0, v0.y, s.y);
        s.z = fmaf(c0, v0.z, s.z); s.w = fmaf(c0, v0.w, s.w);
    }
    reinterpret_cast<float4*>(acc + (long)node * 64)[sub] = s;
}

// =====================================================================
// Incidence scatter (RED-based, ILP-2 x 2 directions) — unchanged.
// =====================================================================
__global__ __launch_bounds__(256) void scatter_inc2(const float* __restrict__ ms,
                                                    const float* __restrict__ mt,
                                                    const int* __restrict__ row,
                                                    const int* __restrict__ col,
                                                    const float* __restrict__ val,
                                                    float* __restrict__ accB0,
                                                    float* __restrict__ accB1, int E) {
    int base = blockIdx.x * 32;
    int tid = threadIdx.x;
    int le = tid >> 4, sub = tid & 15;
    int e0 = base + le;
    int e1 = base + 16 + le;

    int r0 = row[e0], r1 = row[e1];
    int c0 = col[e0], c1 = col[e1];
    float v0 = val[e0], v1 = val[e1];

    float4 a0 = reinterpret_cast<const float4*>(ms + (long)c0 * 64)[sub];
    float4 a1 = reinterpret_cast<const float4*>(ms + (long)c1 * 64)[sub];
    float4 b0 = reinterpret_cast<const float4*>(mt + (long)r0 * 64)[sub];
    float4 b1 = reinterpret_cast<const float4*>(mt + (long)r1 * 64)[sub];

    a0.x *= v0; a0.y *= v0; a0.z *= v0; a0.w *= v0;
    a1.x *= v1; a1.y *= v1; a1.z *= v1; a1.w *= v1;
    b0.x *= v0; b0.y *= v0; b0.z *= v0; b0.w *= v0;
    b1.x *= v1; b1.y *= v1; b1.z *= v1; b1.w *= v1;

    float* pa0 = accB0 + (long)r0 * 64 + sub * 4;
    float* pa1 = accB0 + (long)r1 * 64 + sub * 4;
    float* pb0 = accB1 + (long)c0 * 64 + sub * 4;
    float* pb1 = accB1 + (long)c1 * 64 + sub * 4;
    asm volatile("red.global.add.v4.f32 [%0], {%1,%2,%3,%4};"
                 :: "l"(pa0), "f"(a0.x), "f"(a0.y), "f"(a0.z), "f"(a0.w) : "memory");
    asm volatile("red.global.add.v4.f32 [%0], {%1,%2,%3,%4};"
                 :: "l"(pa1), "f"(a1.x), "f"(a1.y), "f"(a1.z), "f"(a1.w) : "memory");
    asm volatile("red.global.add.v4.f32 [%0], {%1,%2,%3,%4};"
                 :: "l"(pb0), "f"(b0.x), "f"(b0.y), "f"(b0.z), "f"(b0.w) : "memory");
    asm volatile("red.global.add.v4.f32 [%0], {%1,%2,%3,%4};"
                 :: "l"(pb1), "f"(b1.x), "f"(b1.y), "f"(b1.z), "f"(b1.w) : "memory");
}

// ---------------- stream/event pool: LAZY init on first kernel_launch ----------------
static cudaStream_t s1 = 0, s2 = 0, s3 = 0;
static cudaEvent_t eRoot = 0, eB0 = 0, eB1 = 0, eG0 = 0, eG1 = 0, eI = 0, eF0 = 0;
static int g_init_state = 0;

static void ensure_init() {
    if (g_init_state != 0) return;
    bool ok = true;
    ok &= (cudaStreamCreateWithFlags(&s1, cudaStreamNonBlocking) == cudaSuccess);
    ok &= (cudaStreamCreateWithFlags(&s2, cudaStreamNonBlocking) == cudaSuccess);
    ok &= (cudaStreamCreateWithFlags(&s3, cudaStreamNonBlocking) == cudaSuccess);
    ok &= (cudaEventCreateWithFlags(&eRoot, cudaEventDisableTiming) == cudaSuccess);
    ok &= (cudaEventCreateWithFlags(&eB0, cudaEventDisableTiming) == cudaSuccess);
    ok &= (cudaEventCreateWithFlags(&eB1, cudaEventDisableTiming) == cudaSuccess);
    ok &= (cudaEventCreateWithFlags(&eG0, cudaEventDisableTiming) == cudaSuccess);
    ok &= (cudaEventCreateWithFlags(&eG1, cudaEventDisableTiming) == cudaSuccess);
    ok &= (cudaEventCreateWithFlags(&eI, cudaEventDisableTiming) == cudaSuccess);
    ok &= (cudaEventCreateWithFlags(&eF0, cudaEventDisableTiming) == cudaSuccess);
    g_init_state = ok ? 1 : -1;
}

// ---------------- launch ----------------
extern "C" void kernel_launch(void* const* d_in, const int* in_sizes, int n_in,
                              void* d_out, int out_size) {
    ensure_init();

    const float* x0   = (const float*)d_in[0];
    const float* x1   = (const float*)d_in[1];
    const float* x2   = (const float*)d_in[2];
    const float* x3   = (const float*)d_in[3];
    const float* x4   = (const float*)d_in[4];
    const int*   adj0 = (const int*)d_in[5];
    const float* adj0v= (const float*)d_in[6];
    const int*   adj1 = (const int*)d_in[7];
    const float* adj1v= (const float*)d_in[8];
    const int*   inc  = (const int*)d_in[9];
    const float* incv = (const float*)d_in[10];
    const float* cci0 = (const float*)d_in[11];
    const float* cci1 = (const float*)d_in[12];
    const float* Whbs0= (const float*)d_in[13];
    const float* ahbs0= (const float*)d_in[14];
    const float* Whbs1= (const float*)d_in[15];
    const float* ahbs1= (const float*)d_in[16];
    const float* Ws   = (const float*)d_in[17];
    const float* Wt   = (const float*)d_in[18];
    const float* Wag0 = (const float*)d_in[19];
    const float* Wag1 = (const float*)d_in[20];
    float* out = (float*)d_out;

    float *pm0, *pm1, *pms, *pmt, *pA0, *pB0, *pA1, *pB1;
    int *pdeg0, *poff0, *pcur0, *pdeg1, *poff1, *pcur1, *pbs;
    int2 *pcsr0, *pcsr1;
    cudaGetSymbolAddress((void**)&pm0, g_m0);
    cudaGetSymbolAddress((void**)&pm1, g_m1);
    cudaGetSymbolAddress((void**)&pms, g_ms);
    cudaGetSymbolAddress((void**)&pmt, g_mt);
    cudaGetSymbolAddress((void**)&pA0, g_accA0);
    cudaGetSymbolAddress((void**)&pB0, g_accB0);
    cudaGetSymbolAddress((void**)&pA1, g_accA1);
    cudaGetSymbolAddress((void**)&pB1, g_accB1);
    cudaGetSymbolAddress((void**)&pdeg0, g_deg0);
    cudaGetSymbolAddress((void**)&poff0, g_off0);
    cudaGetSymbolAddress((void**)&pcur0, g_cur0);
    cudaGetSymbolAddress((void**)&pdeg1, g_deg1);
    cudaGetSymbolAddress((void**)&poff1, g_off1);
    cudaGetSymbolAddress((void**)&pcur1, g_cur1);
    cudaGetSymbolAddress((void**)&pbs, g_bsum);
    cudaGetSymbolAddress((void**)&pcsr0, g_csr0);
    cudaGetSymbolAddress((void**)&pcsr1, g_csr1);

    const int nb1 = (CN1 + 1023) / 1024;   // 147
    const int nb0 = (CN0 + 1023) / 1024;   // 49

    if (g_init_state == 1) {
        // ---- fork ----
        cudaEventRecord(eRoot, 0);
        cudaStreamWaitEvent(s1, eRoot, 0);
        cudaStreamWaitEvent(s2, eRoot, 0);
        cudaStreamWaitEvent(s3, eRoot, 0);

        // s2: CSR build for E1 then E0 (depends only on adjacency inputs)
        cudaMemsetAsync(pdeg1, 0, sizeof(int) * CN1, s2);
        hist_kernel<<<(CE1 + 255) / 256, 256, 0, s2>>>(adj1 + CE1, pdeg1, CE1);
        scan_block<<<nb1, 1024, 0, s2>>>(pdeg1, poff1, pbs, CN1);
        scan_top<<<1, 256, 0, s2>>>(pbs, nb1);
        scan_add<<<(CN1 + 255) / 256, 256, 0, s2>>>(poff1, pbs, pcur1, CN1);
        reorder_adj<<<(CE1 + 255) / 256, 256, 0, s2>>>(adj1, adj1 + CE1, adj1v, cci1,
                                                       ahbs1, pcur1, pcsr1, CE1);
        cudaEventRecord(eB1, s2);
        cudaMemsetAsync(pdeg0, 0, sizeof(int) * CN0, s2);
        hist_kernel<<<(CE0 + 255) / 256, 256, 0, s2>>>(adj0 + CE0, pdeg0, CE0);
        scan_block<<<nb0, 1024, 0, s2>>>(pdeg0, poff0, pbs, CN0);
        scan_top<<<1, 256, 0, s2>>>(pbs, nb0);
        scan_add<<<(CN0 + 255) / 256, 256, 0, s2>>>(poff0, pbs, pcur0, CN0);
        reorder_adj<<<(CE0 + 255) / 256, 256, 0, s2>>>(adj0, adj0 + CE0, adj0v, cci0,
                                                       ahbs0, pcur0, pcsr0, CE0);
        cudaEventRecord(eB0, s2);

        // s1: chain0 — gemm(x0), then CSR accumulate, later fused0
        gemm64_dual<<<(CN0 + 127) / 128, 256, 0, s1>>>(x0, Whbs0, Wt, pm0, pmt, CN0);
        cudaEventRecord(eG0, s1);

        // main: chain1 — gemm(x1)
        gemm64_dual<<<(CN1 + 127) / 128, 256, 0, 0>>>(x1, Whbs1, Ws, pm1, pms, CN1);
        cudaEventRecord(eG1, 0);

        // s3: memset B accumulators + pass-through copies, then incidence scatter
        cudaMemsetAsync(pB0, 0, sizeof(float) * (size_t)CN0 * DD, s3);
        cudaMemsetAsync(pB1, 0, sizeof(float) * (size_t)CN1 * DD, s3);
        cudaMemcpyAsync(out + (long)(CN0 + CN1) * DD, x2, sizeof(float) * (size_t)CN2 * DD,
                        cudaMemcpyDeviceToDevice, s3);
        cudaMemcpyAsync(out + (long)(CN0 + CN1 + CN2) * DD, x3, sizeof(float) * (size_t)CN3 * DD,
                        cudaMemcpyDeviceToDevice, s3);
        cudaMemcpyAsync(out + (long)(CN0 + CN1 + CN2 + CN3) * DD, x4,
                        sizeof(float) * (size_t)CN4 * DD, cudaMemcpyDeviceToDevice, s3);
        cudaStreamWaitEvent(s3, eG0, 0);
        cudaStreamWaitEvent(s3, eG1, 0);
        scatter_inc2<<<CNNZ / 32, 256, 0, s3>>>(pms, pmt, inc, inc + CNNZ, incv,
                                                pB0, pB1, CNNZ);
        cudaEventRecord(eI, s3);

        // s1: csr_accum0 (gemm0 in-stream, build0 via eB0) then fused0
        cudaStreamWaitEvent(s1, eB0, 0);
        csr_accum<<<CN0 / 16, 256, 0, s1>>>(poff0, pdeg0, pcsr0, pm0, pA0, CN0);
        cudaStreamWaitEvent(s1, eI, 0);
        gemm64_fused<<<(CN0 + 127) / 128, 256, 0, s1>>>(pA0, pB0, Wag0, out, CN0);
        cudaEventRecord(eF0, s1);

        // main: csr_accum1 (gemm1 in-stream, build1 via eB1) then fused1, join
        cudaStreamWaitEvent(0, eB1, 0);
        csr_accum<<<CN1 / 16, 256, 0, 0>>>(poff1, pdeg1, pcsr1, pm1, pA1, CN1);
        cudaStreamWaitEvent(0, eI, 0);
        gemm64_fused<<<(CN1 + 127) / 128, 256, 0, 0>>>(pA1, pB1, Wag1,
                                                       out + (long)CN0 * DD, CN1);
        cudaStreamWaitEvent(0, eF0, 0);  // joins s1 (s2 via eB1/eB0, s3 via eI)
    } else {
        // ======== serial fallback ========
        cudaMemsetAsync(pB0, 0, sizeof(float) * (size_t)CN0 * DD);
        cudaMemsetAsync(pB1, 0, sizeof(float) * (size_t)CN1 * DD);
        cudaMemsetAsync(pdeg1, 0, sizeof(int) * CN1);
        hist_kernel<<<(CE1 + 255) / 256, 256>>>(adj1 + CE1, pdeg1, CE1);
        scan_block<<<nb1, 1024>>>(pdeg1, poff1, pbs, CN1);
        scan_top<<<1, 256>>>(pbs, nb1);
        scan_add<<<(CN1 + 255) / 256, 256>>>(poff1, pbs, pcur1, CN1);
        reorder_adj<<<(CE1 + 255) / 256, 256>>>(adj1, adj1 + CE1, adj1v, cci1,
                                                ahbs1, pcur1, pcsr1, CE1);
        cudaMemsetAsync(pdeg0, 0, sizeof(int) * CN0);
        hist_kernel<<<(CE0 + 255) / 256, 256>>>(adj0 + CE0, pdeg0, CE0);
        scan_block<<<nb0, 1024>>>(pdeg0, poff0, pbs, CN0);
        scan_top<<<1, 256>>>(pbs, nb0);
        scan_add<<<(CN0 + 255) / 256, 256>>>(poff0, pbs, pcur0, CN0);
        reorder_adj<<<(CE0 + 255) / 256, 256>>>(adj0, adj0 + CE0, adj0v, cci0,
                                                ahbs0, pcur0, pcsr0, CE0);
        gemm64_dual<<<(CN0 + 127) / 128, 256>>>(x0, Whbs0, Wt, pm0, pmt, CN0);
        gemm64_dual<<<(CN1 + 127) / 128, 256>>>(x1, Whbs1, Ws, pm1, pms, CN1);
        csr_accum<<<CN0 / 16, 256>>>(poff0, pdeg0, pcsr0, pm0, pA0, CN0);
        csr_accum<<<CN1 / 16, 256>>>(poff1, pdeg1, pcsr1, pm1, pA1, CN1);
        scatter_inc2<<<CNNZ / 32, 256>>>(pms, pmt, inc, inc + CNNZ, incv, pB0, pB1, CNNZ);
        gemm64_fused<<<(CN0 + 127) / 128, 256>>>(pA0, pB0, Wag0, out, CN0);
        gemm64_fused<<<(CN1 + 127) / 128, 256>>>(pA1, pB1, Wag1, out + (long)CN0 * DD, CN1);
        cudaMemcpyAsync(out + (long)(CN0 + CN1) * DD, x2, sizeof(float) * (size_t)CN2 * DD,
                        cudaMemcpyDeviceToDevice);
        cudaMemcpyAsync(out + (long)(CN0 + CN1 + CN2) * DD, x3, sizeof(float) * (size_t)CN3 * DD,
                        cudaMemcpyDeviceToDevice);
        cudaMemcpyAsync(out + (long)(CN0 + CN1 + CN2 + CN3) * DD, x4,
                        sizeof(float) * (size_t)CN4 * DD, cudaMemcpyDeviceToDevice);
    }
}

// round 15
// speedup vs baseline: 1.0993x; 1.0302x over previous
#include <cuda_runtime.h>

#define CN0 50000
#define CN1 150000
#define CN2 20000
#define CN3 5000
#define CN4 1000
#define CE0 800000
#define CE1 1500000
#define CNNZ 300000
#define DD 64

// ---------------- scratch (static device globals; no allocation) ----------------
__device__ float g_m0[CN0 * DD];
__device__ float g_m1[CN1 * DD];
__device__ float g_ms[CN1 * DD];
__device__ float g_mt[CN0 * DD];
__device__ float g_accA0[CN0 * DD];
__device__ float g_accB0[CN0 * DD];
__device__ float g_accA1[CN1 * DD];
__device__ float g_accB1[CN1 * DD];
// CSR scratch (separate bsum per graph; builds can run concurrently)
__device__ int  g_deg0[CN0], g_off0[CN0], g_cur0[CN0];
__device__ int  g_deg1[CN1], g_off1[CN1], g_cur1[CN1];
__device__ int2 g_csr0[CE0];   // {src, coeff_bits} sorted by dst
__device__ int2 g_csr1[CE1];
__device__ int  g_bsum0[256];
__device__ int  g_bsum1[256];

// ---------------- packed f32x2 helpers (Blackwell FFMA2) ----------------
__device__ __forceinline__ unsigned long long pack2(float x, float y) {
    unsigned long long r;
    asm("mov.b64 %0, {%1,%2};" : "=l"(r) : "f"(x), "f"(y));
    return r;
}
__device__ __forceinline__ void fma2(unsigned long long& d, unsigned long long a,
                                     unsigned long long b) {
    asm("fma.rn.f32x2 %0, %1, %2, %0;" : "+l"(d) : "l"(a), "l"(b));
}
__device__ __forceinline__ float2 unpack2(unsigned long long v) {
    float2 f;
    asm("mov.b64 {%0,%1}, %2;" : "=f"(f.x), "=f"(f.y) : "l"(v));
    return f;
}

// =====================================================================
// Dual GEMM: out1 = X@W1, out2 = X@W2.  128 rows/block, 256 threads.
// =====================================================================
__global__ __launch_bounds__(256) void gemm64_dual(const float* __restrict__ X,
                                                   const float* __restrict__ W1,
                                                   const float* __restrict__ W2,
                                                   float* __restrict__ out1,
                                                   float* __restrict__ out2, int N) {
    __shared__ __align__(16) float sW1[64 * 64];
    __shared__ __align__(16) float sW2[64 * 64];
    __shared__ __align__(16) float sXT[128 * 64];
    int tid = threadIdx.x;
#pragma unroll
    for (int i = 0; i < 16; i++) {
        sW1[tid + i * 256] = W1[tid + i * 256];
        sW2[tid + i * 256] = W2[tid + i * 256];
    }
    long r0 = (long)blockIdx.x * 128;
#pragma unroll
    for (int i = 0; i < 32; i++) {
        int li = tid + i * 256;
        int row = li >> 6, col = li & 63;
        long gr = r0 + row;
        float v = (gr < N) ? X[gr * 64 + col] : 0.f;
        sXT[col * 128 + (((row >> 2) ^ (col & 31)) << 2) + (row & 3)] = v;
    }
    __syncthreads();

    int tx = tid & 15, ty = tid >> 4;
    unsigned long long a1[8][2], a2[8][2];
#pragma unroll
    for (int r = 0; r < 8; r++) { a1[r][0] = a1[r][1] = a2[r][0] = a2[r][1] = 0ull; }

    const float4* sXT4 = (const float4*)sXT;
    const ulonglong2* sW1v = (const ulonglong2*)sW1;
    const ulonglong2* sW2v = (const ulonglong2*)sW2;
    int g0 = 2 * ty, g1 = 2 * ty + 1;
#pragma unroll 8
    for (int k = 0; k < 64; k++) {
        float4 xa = sXT4[k * 32 + (g0 ^ (k & 31))];
        float4 xb = sXT4[k * 32 + (g1 ^ (k & 31))];
        ulonglong2 w1 = sW1v[k * 16 + tx];
        ulonglong2 w2 = sW2v[k * 16 + tx];
        float xs[8] = {xa.x, xa.y, xa.z, xa.w, xb.x, xb.y, xb.z, xb.w};
#pragma unroll
        for (int r = 0; r < 8; r++) {
            unsigned long long xx = pack2(xs[r], xs[r]);
            fma2(a1[r][0], xx, w1.x); fma2(a1[r][1], xx, w1.y);
            fma2(a2[r][0], xx, w2.x); fma2(a2[r][1], xx, w2.y);
        }
    }
#pragma unroll
    for (int r = 0; r < 8; r++) {
        long row = r0 + ty * 8 + r;
        if (row < N) {
            float2 lo = unpack2(a1[r][0]), hi = unpack2(a1[r][1]);
            ((float4*)out1)[row * 16 + tx] = make_float4(lo.x, lo.y, hi.x, hi.y);
            lo = unpack2(a2[r][0]); hi = unpack2(a2[r][1]);
            ((float4*)out2)[row * 16 + tx] = make_float4(lo.x, lo.y, hi.x, hi.y);
        }
    }
}

// =====================================================================
// Fused epilogue: out = relu((relu(A)+relu(B)) @ W)
// =====================================================================
__global__ __launch_bounds__(256) void gemm64_fused(const float* __restrict__ A,
                                                    const float* __restrict__ B,
                                                    const float* __restrict__ W,
                                                    float* __restrict__ out, int N) {
    __shared__ __align__(16) float sW[64 * 64];
    __shared__ __align__(16) float sXT[128 * 64];
    int tid = threadIdx.x;
#pragma unroll
    for (int i = 0; i < 16; i++) sW[tid + i * 256] = W[tid + i * 256];
    long r0 = (long)blockIdx.x * 128;
#pragma unroll
    for (int i = 0; i < 32; i++) {
        int li = tid + i * 256;
        int row = li >> 6, col = li & 63;
        long gr = r0 + row;
        float v = 0.f;
        if (gr < N) {
            long idx = gr * 64 + col;
            v = fmaxf(A[idx], 0.f) + fmaxf(B[idx], 0.f);
        }
        sXT[col * 128 + (((row >> 2) ^ (col & 31)) << 2) + (row & 3)] = v;
    }
    __syncthreads();

    int tx = tid & 15, ty = tid >> 4;
    unsigned long long a1[8][2];
#pragma unroll
    for (int r = 0; r < 8; r++) { a1[r][0] = a1[r][1] = 0ull; }

    const float4* sXT4 = (const float4*)sXT;
    const ulonglong2* sWv = (const ulonglong2*)sW;
    int g0 = 2 * ty, g1 = 2 * ty + 1;
#pragma unroll 8
    for (int k = 0; k < 64; k++) {
        float4 xa = sXT4[k * 32 + (g0 ^ (k & 31))];
        float4 xb = sXT4[k * 32 + (g1 ^ (k & 31))];
        ulonglong2 w = sWv[k * 16 + tx];
        float xs[8] = {xa.x, xa.y, xa.z, xa.w, xb.x, xb.y, xb.z, xb.w};
#pragma unroll
        for (int r = 0; r < 8; r++) {
            unsigned long long xx = pack2(xs[r], xs[r]);
            fma2(a1[r][0], xx, w.x); fma2(a1[r][1], xx, w.y);
        }
    }
#pragma unroll
    for (int r = 0; r < 8; r++) {
        long row = r0 + ty * 8 + r;
        if (row < N) {
            float2 lo = unpack2(a1[r][0]), hi = unpack2(a1[r][1]);
            ((float4*)out)[row * 16 + tx] =
                make_float4(fmaxf(lo.x, 0.f), fmaxf(lo.y, 0.f),
                            fmaxf(hi.x, 0.f), fmaxf(hi.y, 0.f));
        }
    }
}

// ======================= CSR build kernels =======================
__global__ __launch_bounds__(256) void hist_kernel(const int* __restrict__ dst,
                                                   int* __restrict__ deg, int E) {
    int e = blockIdx.x * blockDim.x + threadIdx.x;
    if (e < E) atomicAdd(&deg[dst[e]], 1);
}

__global__ __launch_bounds__(1024) void scan_block(const int* __restrict__ in,
                                                   int* __restrict__ out,
                                                   int* __restrict__ bsum, int N) {
    __shared__ int s[1024];
    int gid = blockIdx.x * 1024 + threadIdx.x;
    int v = (gid < N) ? in[gid] : 0;
    s[threadIdx.x] = v;
    __syncthreads();
#pragma unroll
    for (int d = 1; d < 1024; d <<= 1) {
        int t = (threadIdx.x >= d) ? s[threadIdx.x - d] : 0;
        __syncthreads();
        s[threadIdx.x] += t;
        __syncthreads();
    }
    if (gid < N) out[gid] = s[threadIdx.x] - v;  // exclusive
    if (threadIdx.x == 1023) bsum[blockIdx.x] = s[1023];
}

__global__ __launch_bounds__(256) void scan_top(int* __restrict__ bsum, int nb) {
    __shared__ int s[256];
    int v = (threadIdx.x < nb) ? bsum[threadIdx.x] : 0;
    s[threadIdx.x] = v;
    __syncthreads();
#pragma unroll
    for (int d = 1; d < 256; d <<= 1) {
        int t = (threadIdx.x >= d) ? s[threadIdx.x - d] : 0;
        __syncthreads();
        s[threadIdx.x] += t;
        __syncthreads();
    }
    if (threadIdx.x < nb) bsum[threadIdx.x] = s[threadIdx.x] - v;
}

__global__ __launch_bounds__(256) void scan_add(int* __restrict__ off,
                                                const int* __restrict__ bsum,
                                                int* __restrict__ cur, int N) {
    int gid = blockIdx.x * blockDim.x + threadIdx.x;
    if (gid < N) {
        int o = off[gid] + bsum[gid >> 10];
        off[gid] = o;
        cur[gid] = o;
    }
}

__global__ __launch_bounds__(256) void reorder_adj(const int* __restrict__ src,
                                                   const int* __restrict__ dst,
                                                   const float* __restrict__ val,
                                                   const float* __restrict__ cci,
                                                   const float* __restrict__ a,
                                                   int* __restrict__ cur,
                                                   int2* __restrict__ csr, int E) {
    int e = blockIdx.x * blockDim.x + threadIdx.x;
    if (e >= E) return;
    float c = val[e] * (cci[e * 3 + 0] * a[0] + cci[e * 3 + 1] * a[1] +
                        cci[e * 3 + 2] * a[2]);
    int pos = atomicAdd(&cur[dst[e]], 1);
    csr[pos] = make_int2(src[e], __float_as_int(c));
}

// =====================================================================
// CSR gather-side segment sum: 16 lanes/node, register accumulator,
// unroll-4 edge loop (4 outstanding gathers), single STG.128 per node.
// =====================================================================
__global__ __launch_bounds__(256) void csr_accum(const int* __restrict__ off,
                                                 const int* __restrict__ deg,
                                                 const int2* __restrict__ csr,
                                                 const float* __restrict__ m,
                                                 float* __restrict__ acc, int N) {
    int tid = threadIdx.x;
    int node = blockIdx.x * 16 + (tid >> 4);
    int sub = tid & 15;
    int start = off[node];
    int d = deg[node];
    float4 s = make_float4(0.f, 0.f, 0.f, 0.f);
    int j = 0;
    for (; j + 4 <= d; j += 4) {
        int2 e0 = csr[start + j];
        int2 e1 = csr[start + j + 1];
        int2 e2 = csr[start + j + 2];
        int2 e3 = csr[start + j + 3];
        float4 v0 = reinterpret_cast<const float4*>(m + (long)e0.x * 64)[sub];
        float4 v1 = reinterpret_cast<const float4*>(m + (long)e1.x * 64)[sub];
        float4 v2 = reinterpret_cast<const float4*>(m + (long)e2.x * 64)[sub];
        float4 v3 = reinterpret_cast<const float4*>(m + (long)e3.x * 64)[sub];
        float c0 = __int_as_float(e0.y), c1 = __int_as_float(e1.y);
        float c2 = __int_as_float(e2.y), c3 = __int_as_float(e3.y);
        s.x = fmaf(c0, v0.x, s.x); s.y = fmaf(c0, v0.y, s.y);
        s.z = fmaf(c0, v0.z, s.z); s.w = fmaf(c0, v0.w, s.w);
        s.x = fmaf(c1, v1.x, s.x); s.y = fmaf(c1, v1.y, s.y);
        s.z = fmaf(c1, v1.z, s.z); s.w = fmaf(c1, v1.w, s.w);
        s.x = fmaf(c2, v2.x, s.x); s.y = fmaf(c2, v2.y, s.y);
        s.z = fmaf(c2, v2.z, s.z); s.w = fmaf(c2, v2.w, s.w);
        s.x = fmaf(c3, v3.x, s.x); s.y = fmaf(c3, v3.y, s.y);
        s.z = fmaf(c3, v3.z, s.z); s.w = fmaf(c3, v3.w, s.w);
    }
    for (; j < d; j++) {
        int2 e0 = csr[start + j];
        float4 v0 = reinterpret_cast<const float4*>(m + (long)e0.x * 64)[sub];
        float c0 = __int_as_float(e0.y);
        s.x = fmaf(c0, v0.x, s.x); s.y = fmaf(c0, v0.y, s.y);
        s.z = fmaf(c0, v0.z, s.z); s.w = fmaf(c0, v0.w, s.w);
    }
    reinterpret_cast<float4*>(acc + (long)node * 64)[sub] = s;
}

// =====================================================================
// Incidence scatter (RED-based, ILP-2 x 2 directions).
// =====================================================================
__global__ __launch_bounds__(256) void scatter_inc2(const float* __restrict__ ms,
                                                    const float* __restrict__ mt,
                                                    const int* __restrict__ row,
                                                    const int* __restrict__ col,
                                                    const float* __restrict__ val,
                                                    float* __restrict__ accB0,
                                                    float* __restrict__ accB1, int E) {
    int base = blockIdx.x * 32;
    int tid = threadIdx.x;
    int le = tid >> 4, sub = tid & 15;
    int e0 = base + le;
    int e1 = base + 16 + le;

    int r0 = row[e0], r1 = row[e1];
    int c0 = col[e0], c1 = col[e1];
    float v0 = val[e0], v1 = val[e1];

    float4 a0 = reinterpret_cast<const float4*>(ms + (long)c0 * 64)[sub];
    float4 a1 = reinterpret_cast<const float4*>(ms + (long)c1 * 64)[sub];
    float4 b0 = reinterpret_cast<const float4*>(mt + (long)r0 * 64)[sub];
    float4 b1 = reinterpret_cast<const float4*>(mt + (long)r1 * 64)[sub];

    a0.x *= v0; a0.y *= v0; a0.z *= v0; a0.w *= v0;
    a1.x *= v1; a1.y *= v1; a1.z *= v1; a1.w *= v1;
    b0.x *= v0; b0.y *= v0; b0.z *= v0; b0.w *= v0;
    b1.x *= v1; b1.y *= v1; b1.z *= v1; b1.w *= v1;

    float* pa0 = accB0 + (long)r0 * 64 + sub * 4;
    float* pa1 = accB0 + (long)r1 * 64 + sub * 4;
    float* pb0 = accB1 + (long)c0 * 64 + sub * 4;
    float* pb1 = accB1 + (long)c1 * 64 + sub * 4;
    asm volatile("red.global.add.v4.f32 [%0], {%1,%2,%3,%4};"
                 :: "l"(pa0), "f"(a0.x), "f"(a0.y), "f"(a0.z), "f"(a0.w) : "memory");
    asm volatile("red.global.add.v4.f32 [%0], {%1,%2,%3,%4};"
                 :: "l"(pa1), "f"(a1.x), "f"(a1.y), "f"(a1.z), "f"(a1.w) : "memory");
    asm volatile("red.global.add.v4.f32 [%0], {%1,%2,%3,%4};"
                 :: "l"(pb0), "f"(b0.x), "f"(b0.y), "f"(b0.z), "f"(b0.w) : "memory");
    asm volatile("red.global.add.v4.f32 [%0], {%1,%2,%3,%4};"
                 :: "l"(pb1), "f"(b1.x), "f"(b1.y), "f"(b1.z), "f"(b1.w) : "memory");
}

// ---------------- stream/event pool: LAZY init, 3 streams (R12 footprint) ----------------
static cudaStream_t s1 = 0, s2 = 0, s3 = 0;
static cudaEvent_t eRoot = 0, eB1 = 0, eG0 = 0, eG1 = 0, eI = 0, eF0 = 0;
static int g_init_state = 0;

static void ensure_init() {
    if (g_init_state != 0) return;
    bool ok = true;
    ok &= (cudaStreamCreateWithFlags(&s1, cudaStreamNonBlocking) == cudaSuccess);
    ok &= (cudaStreamCreateWithFlags(&s2, cudaStreamNonBlocking) == cudaSuccess);
    ok &= (cudaStreamCreateWithFlags(&s3, cudaStreamNonBlocking) == cudaSuccess);
    ok &= (cudaEventCreateWithFlags(&eRoot, cudaEventDisableTiming) == cudaSuccess);
    ok &= (cudaEventCreateWithFlags(&eB1, cudaEventDisableTiming) == cudaSuccess);
    ok &= (cudaEventCreateWithFlags(&eG0, cudaEventDisableTiming) == cudaSuccess);
    ok &= (cudaEventCreateWithFlags(&eG1, cudaEventDisableTiming) == cudaSuccess);
    ok &= (cudaEventCreateWithFlags(&eI, cudaEventDisableTiming) == cudaSuccess);
    ok &= (cudaEventCreateWithFlags(&eF0, cudaEventDisableTiming) == cudaSuccess);
    g_init_state = ok ? 1 : -1;
}

// ---------------- launch ----------------
extern "C" void kernel_launch(void* const* d_in, const int* in_sizes, int n_in,
                              void* d_out, int out_size) {
    ensure_init();

    const float* x0   = (const float*)d_in[0];
    const float* x1   = (const float*)d_in[1];
    const float* x2   = (const float*)d_in[2];
    const float* x3   = (const float*)d_in[3];
    const float* x4   = (const float*)d_in[4];
    const int*   adj0 = (const int*)d_in[5];
    const float* adj0v= (const float*)d_in[6];
    const int*   adj1 = (const int*)d_in[7];
    const float* adj1v= (const float*)d_in[8];
    const int*   inc  = (const int*)d_in[9];
    const float* incv = (const float*)d_in[10];
    const float* cci0 = (const float*)d_in[11];
    const float* cci1 = (const float*)d_in[12];
    const float* Whbs0= (const float*)d_in[13];
    const float* ahbs0= (const float*)d_in[14];
    const float* Whbs1= (const float*)d_in[15];
    const float* ahbs1= (const float*)d_in[16];
    const float* Ws   = (const float*)d_in[17];
    const float* Wt   = (const float*)d_in[18];
    const float* Wag0 = (const float*)d_in[19];
    const float* Wag1 = (const float*)d_in[20];
    float* out = (float*)d_out;

    float *pm0, *pm1, *pms, *pmt, *pA0, *pB0, *pA1, *pB1;
    int *pdeg0, *poff0, *pcur0, *pdeg1, *poff1, *pcur1, *pbs0, *pbs1;
    int2 *pcsr0, *pcsr1;
    cudaGetSymbolAddress((void**)&pm0, g_m0);
    cudaGetSymbolAddress((void**)&pm1, g_m1);
    cudaGetSymbolAddress((void**)&pms, g_ms);
    cudaGetSymbolAddress((void**)&pmt, g_mt);
    cudaGetSymbolAddress((void**)&pA0, g_accA0);
    cudaGetSymbolAddress((void**)&pB0, g_accB0);
    cudaGetSymbolAddress((void**)&pA1, g_accA1);
    cudaGetSymbolAddress((void**)&pB1, g_accB1);
    cudaGetSymbolAddress((void**)&pdeg0, g_deg0);
    cudaGetSymbolAddress((void**)&poff0, g_off0);
    cudaGetSymbolAddress((void**)&pcur0, g_cur0);
    cudaGetSymbolAddress((void**)&pdeg1, g_deg1);
    cudaGetSymbolAddress((void**)&poff1, g_off1);
    cudaGetSymbolAddress((void**)&pcur1, g_cur1);
    cudaGetSymbolAddress((void**)&pbs0, g_bsum0);
    cudaGetSymbolAddress((void**)&pbs1, g_bsum1);
    cudaGetSymbolAddress((void**)&pcsr0, g_csr0);
    cudaGetSymbolAddress((void**)&pcsr1, g_csr1);

    const int nb1 = (CN1 + 1023) / 1024;   // 147
    const int nb0 = (CN0 + 1023) / 1024;   // 49

    if (g_init_state == 1) {
        // ---- fork ----
        cudaEventRecord(eRoot, 0);
        cudaStreamWaitEvent(s1, eRoot, 0);
        cudaStreamWaitEvent(s2, eRoot, 0);
        cudaStreamWaitEvent(s3, eRoot, 0);

        // s2: CSR build for E1 (critical: feeds csr_accum1 on main)
        cudaMemsetAsync(pdeg1, 0, sizeof(int) * CN1, s2);
        hist_kernel<<<(CE1 + 255) / 256, 256, 0, s2>>>(adj1 + CE1, pdeg1, CE1);
        scan_block<<<nb1, 1024, 0, s2>>>(pdeg1, poff1, pbs1, CN1);
        scan_top<<<1, 256, 0, s2>>>(pbs1, nb1);
        scan_add<<<(CN1 + 255) / 256, 256, 0, s2>>>(poff1, pbs1, pcur1, CN1);
        reorder_adj<<<(CE1 + 255) / 256, 256, 0, s2>>>(adj1, adj1 + CE1, adj1v, cci1,
                                                       ahbs1, pcur1, pcsr1, CE1);
        cudaEventRecord(eB1, s2);

        // s1: chain0 entirely in-stream — build0, gemm0, csr_accum0, fused0
        cudaMemsetAsync(pdeg0, 0, sizeof(int) * CN0, s1);
        hist_kernel<<<(CE0 + 255) / 256, 256, 0, s1>>>(adj0 + CE0, pdeg0, CE0);
        scan_block<<<nb0, 1024, 0, s1>>>(pdeg0, poff0, pbs0, CN0);
        scan_top<<<1, 256, 0, s1>>>(pbs0, nb0);
        scan_add<<<(CN0 + 255) / 256, 256, 0, s1>>>(poff0, pbs0, pcur0, CN0);
        reorder_adj<<<(CE0 + 255) / 256, 256, 0, s1>>>(adj0, adj0 + CE0, adj0v, cci0,
                                                       ahbs0, pcur0, pcsr0, CE0);
        gemm64_dual<<<(CN0 + 127) / 128, 256, 0, s1>>>(x0, Whbs0, Wt, pm0, pmt, CN0);
        cudaEventRecord(eG0, s1);
        csr_accum<<<CN0 / 16, 256, 0, s1>>>(poff0, pdeg0, pcsr0, pm0, pA0, CN0);

        // main: chain1 — gemm(x1)
        gemm64_dual<<<(CN1 + 127) / 128, 256, 0, 0>>>(x1, Whbs1, Ws, pm1, pms, CN1);
        cudaEventRecord(eG1, 0);

        // s3: memset B accumulators + pass-through copies, then incidence scatter
        cudaMemsetAsync(pB0, 0, sizeof(float) * (size_t)CN0 * DD, s3);
        cudaMemsetAsync(pB1, 0, sizeof(float) * (size_t)CN1 * DD, s3);
        cudaMemcpyAsync(out + (long)(CN0 + CN1) * DD, x2, sizeof(float) * (size_t)CN2 * DD,
                        cudaMemcpyDeviceToDevice, s3);
        cudaMemcpyAsync(out + (long)(CN0 + CN1 + CN2) * DD, x3, sizeof(float) * (size_t)CN3 * DD,
                        cudaMemcpyDeviceToDevice, s3);
        cudaMemcpyAsync(out + (long)(CN0 + CN1 + CN2 + CN3) * DD, x4,
                        sizeof(float) * (size_t)CN4 * DD, cudaMemcpyDeviceToDevice, s3);
        cudaStreamWaitEvent(s3, eG0, 0);
        cudaStreamWaitEvent(s3, eG1, 0);
        scatter_inc2<<<CNNZ / 32, 256, 0, s3>>>(pms, pmt, inc, inc + CNNZ, incv,
                                                pB0, pB1, CNNZ);
        cudaEventRecord(eI, s3);

        // s1: fused0 after incidence scatter
        cudaStreamWaitEvent(s1, eI, 0);
        gemm64_fused<<<(CN0 + 127) / 128, 256, 0, s1>>>(pA0, pB0, Wag0, out, CN0);
        cudaEventRecord(eF0, s1);

        // main: csr_accum1 (gemm1 in-stream, build1 via eB1) then fused1, join
        cudaStreamWaitEvent(0, eB1, 0);
        csr_accum<<<CN1 / 16, 256, 0, 0>>>(poff1, pdeg1, pcsr1, pm1, pA1, CN1);
        cudaStreamWaitEvent(0, eI, 0);
        gemm64_fused<<<(CN1 + 127) / 128, 256, 0, 0>>>(pA1, pB1, Wag1,
                                                       out + (long)CN0 * DD, CN1);
        cudaStreamWaitEvent(0, eF0, 0);  // joins s1 (s2 via eB1, s3 via eI)
    } else {
        // ======== serial fallback ========
        cudaMemsetAsync(pB0, 0, sizeof(float) * (size_t)CN0 * DD);
        cudaMemsetAsync(pB1, 0, sizeof(float) * (size_t)CN1 * DD);
        cudaMemsetAsync(pdeg1, 0, sizeof(int) * CN1);
        hist_kernel<<<(CE1 + 255) / 256, 256>>>(adj1 + CE1, pdeg1, CE1);
        scan_block<<<nb1, 1024>>>(pdeg1, poff1, pbs1, CN1);
        scan_top<<<1, 256>>>(pbs1, nb1);
        scan_add<<<(CN1 + 255) / 256, 256>>>(poff1, pbs1, pcur1, CN1);
        reorder_adj<<<(CE1 + 255) / 256, 256>>>(adj1, adj1 + CE1, adj1v, cci1,
                                                ahbs1, pcur1, pcsr1, CE1);
        cudaMemsetAsync(pdeg0, 0, sizeof(int) * CN0);
        hist_kernel<<<(CE0 + 255) / 256, 256>>>(adj0 + CE0, pdeg0, CE0);
        scan_block<<<nb0, 1024>>>(pdeg0, poff0, pbs0, CN0);
        scan_top<<<1, 256>>>(pbs0, nb0);
        scan_add<<<(CN0 + 255) / 256, 256>>>(poff0, pbs0, pcur0, CN0);
        reorder_adj<<<(CE0 + 255) / 256, 256>>>(adj0, adj0 + CE0, adj0v, cci0,
                                                ahbs0, pcur0, pcsr0, CE0);
        gemm64_dual<<<(CN0 + 127) / 128, 256>>>(x0, Whbs0, Wt, pm0, pmt, CN0);
        gemm64_dual<<<(CN1 + 127) / 128, 256>>>(x1, Whbs1, Ws, pm1, pms, CN1);
        csr_accum<<<CN0 / 16, 256>>>(poff0, pdeg0, pcsr0, pm0, pA0, CN0);
        csr_accum<<<CN1 / 16, 256>>>(poff1, pdeg1, pcsr1, pm1, pA1, CN1);
        scatter_inc2<<<CNNZ / 32, 256>>>(pms, pmt, inc, inc + CNNZ, incv, pB0, pB1, CNNZ);
        gemm64_fused<<<(CN0 + 127) / 128, 256>>>(pA0, pB0, Wag0, out, CN0);
        gemm64_fused<<<(CN1 + 127) / 128, 256>>>(pA1, pB1, Wag1, out + (long)CN0 * DD, CN1);
        cudaMemcpyAsync(out + (long)(CN0 + CN1) * DD, x2, sizeof(float) * (size_t)CN2 * DD,
                        cudaMemcpyDeviceToDevice);
        cudaMemcpyAsync(out + (long)(CN0 + CN1 + CN2) * DD, x3, sizeof(float) * (size_t)CN3 * DD,
                        cudaMemcpyDeviceToDevice);
        cudaMemcpyAsync(out + (long)(CN0 + CN1 + CN2 + CN3) * DD, x4,
                        sizeof(float) * (size_t)CN4 * DD, cudaMemcpyDeviceToDevice);
    }
}

// round 16
// speedup vs baseline: 1.1754x; 1.0692x over previous
#include <cuda_runtime.h>
#include <cuda_fp16.h>

#define CN0 50000
#define CN1 150000
#define CN2 20000
#define CN3 5000
#define CN4 1000
#define CE0 800000
#define CE1 1500000
#define CNNZ 300000
#define DD 64

// ---------------- scratch (static device globals; no allocation) ----------------
__device__ __half g_m0[CN0 * DD];   // fp16 messages (halved gather traffic)
__device__ __half g_m1[CN1 * DD];
__device__ __half g_ms[CN1 * DD];
__device__ __half g_mt[CN0 * DD];
__device__ float g_accA0[CN0 * DD];
__device__ float g_accB0[CN0 * DD];
__device__ float g_accA1[CN1 * DD];
__device__ float g_accB1[CN1 * DD];
// CSR scratch
__device__ int  g_deg0[CN0], g_off0[CN0], g_cur0[CN0];
__device__ int  g_deg1[CN1], g_off1[CN1], g_cur1[CN1];
__device__ int2 g_csr0[CE0];   // {src, coeff_bits} sorted by dst
__device__ int2 g_csr1[CE1];
__device__ int  g_bsum0[256];
__device__ int  g_bsum1[256];

// ---------------- packed f32x2 helpers (Blackwell FFMA2) ----------------
__device__ __forceinline__ unsigned long long pack2(float x, float y) {
    unsigned long long r;
    asm("mov.b64 %0, {%1,%2};" : "=l"(r) : "f"(x), "f"(y));
    return r;
}
__device__ __forceinline__ void fma2(unsigned long long& d, unsigned long long a,
                                     unsigned long long b) {
    asm("fma.rn.f32x2 %0, %1, %2, %0;" : "+l"(d) : "l"(a), "l"(b));
}
__device__ __forceinline__ float2 unpack2(unsigned long long v) {
    float2 f;
    asm("mov.b64 {%0,%1}, %2;" : "=f"(f.x), "=f"(f.y) : "l"(v));
    return f;
}

// fp16 row gather helper: lane 'sub' reads feature cols [4sub..4sub+3] (8 bytes)
__device__ __forceinline__ float4 gather_h4(const __half* __restrict__ m,
                                            long row, int sub) {
    uint2 u = reinterpret_cast<const uint2*>(m + row * 64)[sub];
    __half2 h0 = *reinterpret_cast<__half2*>(&u.x);
    __half2 h1 = *reinterpret_cast<__half2*>(&u.y);
    float2 f0 = __half22float2(h0);
    float2 f1 = __half22float2(h1);
    return make_float4(f0.x, f0.y, f1.x, f1.y);
}

// =====================================================================
// Dual GEMM: out1 = X@W1, out2 = X@W2 (fp16 outputs).  128 rows/block.
// =====================================================================
__global__ __launch_bounds__(256) void gemm64_dual(const float* __restrict__ X,
                                                   const float* __restrict__ W1,
                                                   const float* __restrict__ W2,
                                                   __half* __restrict__ out1,
                                                   __half* __restrict__ out2, int N) {
    __shared__ __align__(16) float sW1[64 * 64];
    __shared__ __align__(16) float sW2[64 * 64];
    __shared__ __align__(16) float sXT[128 * 64];
    int tid = threadIdx.x;
#pragma unroll
    for (int i = 0; i < 16; i++) {
        sW1[tid + i * 256] = W1[tid + i * 256];
        sW2[tid + i * 256] = W2[tid + i * 256];
    }
    long r0 = (long)blockIdx.x * 128;
#pragma unroll
    for (int i = 0; i < 32; i++) {
        int li = tid + i * 256;
        int row = li >> 6, col = li & 63;
        long gr = r0 + row;
        float v = (gr < N) ? X[gr * 64 + col] : 0.f;
        sXT[col * 128 + (((row >> 2) ^ (col & 31)) << 2) + (row & 3)] = v;
    }
    __syncthreads();

    int tx = tid & 15, ty = tid >> 4;
    unsigned long long a1[8][2], a2[8][2];
#pragma unroll
    for (int r = 0; r < 8; r++) { a1[r][0] = a1[r][1] = a2[r][0] = a2[r][1] = 0ull; }

    const float4* sXT4 = (const float4*)sXT;
    const ulonglong2* sW1v = (const ulonglong2*)sW1;
    const ulonglong2* sW2v = (const ulonglong2*)sW2;
    int g0 = 2 * ty, g1 = 2 * ty + 1;
#pragma unroll 8
    for (int k = 0; k < 64; k++) {
        float4 xa = sXT4[k * 32 + (g0 ^ (k & 31))];
        float4 xb = sXT4[k * 32 + (g1 ^ (k & 31))];
        ulonglong2 w1 = sW1v[k * 16 + tx];
        ulonglong2 w2 = sW2v[k * 16 + tx];
        float xs[8] = {xa.x, xa.y, xa.z, xa.w, xb.x, xb.y, xb.z, xb.w};
#pragma unroll
        for (int r = 0; r < 8; r++) {
            unsigned long long xx = pack2(xs[r], xs[r]);
            fma2(a1[r][0], xx, w1.x); fma2(a1[r][1], xx, w1.y);
            fma2(a2[r][0], xx, w2.x); fma2(a2[r][1], xx, w2.y);
        }
    }
#pragma unroll
    for (int r = 0; r < 8; r++) {
        long row = r0 + ty * 8 + r;
        if (row < N) {
            float2 lo = unpack2(a1[r][0]), hi = unpack2(a1[r][1]);
            __half2 h0 = __floats2half2_rn(lo.x, lo.y);
            __half2 h1 = __floats2half2_rn(hi.x, hi.y);
            uint2 o;
            o.x = *reinterpret_cast<unsigned int*>(&h0);
            o.y = *reinterpret_cast<unsigned int*>(&h1);
            reinterpret_cast<uint2*>(out1)[row * 16 + tx] = o;
            lo = unpack2(a2[r][0]); hi = unpack2(a2[r][1]);
            h0 = __floats2half2_rn(lo.x, lo.y);
            h1 = __floats2half2_rn(hi.x, hi.y);
            o.x = *reinterpret_cast<unsigned int*>(&h0);
            o.y = *reinterpret_cast<unsigned int*>(&h1);
            reinterpret_cast<uint2*>(out2)[row * 16 + tx] = o;
        }
    }
}

// =====================================================================
// Fused epilogue: out = relu((relu(A)+relu(B)) @ W)   (fp32 in/out)
// =====================================================================
__global__ __launch_bounds__(256) void gemm64_fused(const float* __restrict__ A,
                                                    const float* __restrict__ B,
                                                    const float* __restrict__ W,
                                                    float* __restrict__ out, int N) {
    __shared__ __align__(16) float sW[64 * 64];
    __shared__ __align__(16) float sXT[128 * 64];
    int tid = threadIdx.x;
#pragma unroll
    for (int i = 0; i < 16; i++) sW[tid + i * 256] = W[tid + i * 256];
    long r0 = (long)blockIdx.x * 128;
#pragma unroll
    for (int i = 0; i < 32; i++) {
        int li = tid + i * 256;
        int row = li >> 6, col = li & 63;
        long gr = r0 + row;
        float v = 0.f;
        if (gr < N) {
            long idx = gr * 64 + col;
            v = fmaxf(A[idx], 0.f) + fmaxf(B[idx], 0.f);
        }
        sXT[col * 128 + (((row >> 2) ^ (col & 31)) << 2) + (row & 3)] = v;
    }
    __syncthreads();

    int tx = tid & 15, ty = tid >> 4;
    unsigned long long a1[8][2];
#pragma unroll
    for (int r = 0; r < 8; r++) { a1[r][0] = a1[r][1] = 0ull; }

    const float4* sXT4 = (const float4*)sXT;
    const ulonglong2* sWv = (const ulonglong2*)sW;
    int g0 = 2 * ty, g1 = 2 * ty + 1;
#pragma unroll 8
    for (int k = 0; k < 64; k++) {
        float4 xa = sXT4[k * 32 + (g0 ^ (k & 31))];
        float4 xb = sXT4[k * 32 + (g1 ^ (k & 31))];
        ulonglong2 w = sWv[k * 16 + tx];
        float xs[8] = {xa.x, xa.y, xa.z, xa.w, xb.x, xb.y, xb.z, xb.w};
#pragma unroll
        for (int r = 0; r < 8; r++) {
            unsigned long long xx = pack2(xs[r], xs[r]);
            fma2(a1[r][0], xx, w.x); fma2(a1[r][1], xx, w.y);
        }
    }
#pragma unroll
    for (int r = 0; r < 8; r++) {
        long row = r0 + ty * 8 + r;
        if (row < N) {
            float2 lo = unpack2(a1[r][0]), hi = unpack2(a1[r][1]);
            ((float4*)out)[row * 16 + tx] =
                make_float4(fmaxf(lo.x, 0.f), fmaxf(lo.y, 0.f),
                            fmaxf(hi.x, 0.f), fmaxf(hi.y, 0.f));
        }
    }
}

// ======================= CSR build kernels =======================
__global__ __launch_bounds__(256) void hist_kernel(const int* __restrict__ dst,
                                                   int* __restrict__ deg, int E) {
    int e = blockIdx.x * blockDim.x + threadIdx.x;
    if (e < E) atomicAdd(&deg[dst[e]], 1);
}

__global__ __launch_bounds__(1024) void scan_block(const int* __restrict__ in,
                                                   int* __restrict__ out,
                                                   int* __restrict__ bsum, int N) {
    __shared__ int s[1024];
    int gid = blockIdx.x * 1024 + threadIdx.x;
    int v = (gid < N) ? in[gid] : 0;
    s[threadIdx.x] = v;
    __syncthreads();
#pragma unroll
    for (int d = 1; d < 1024; d <<= 1) {
        int t = (threadIdx.x >= d) ? s[threadIdx.x - d] : 0;
        __syncthreads();
        s[threadIdx.x] += t;
        __syncthreads();
    }
    if (gid < N) out[gid] = s[threadIdx.x] - v;  // exclusive
    if (threadIdx.x == 1023) bsum[blockIdx.x] = s[1023];
}

__global__ __launch_bounds__(256) void scan_top(int* __restrict__ bsum, int nb) {
    __shared__ int s[256];
    int v = (threadIdx.x < nb) ? bsum[threadIdx.x] : 0;
    s[threadIdx.x] = v;
    __syncthreads();
#pragma unroll
    for (int d = 1; d < 256; d <<= 1) {
        int t = (threadIdx.x >= d) ? s[threadIdx.x - d] : 0;
        __syncthreads();
        s[threadIdx.x] += t;
        __syncthreads();
    }
    if (threadIdx.x < nb) bsum[threadIdx.x] = s[threadIdx.x] - v;
}

__global__ __launch_bounds__(256) void scan_add(int* __restrict__ off,
                                                const int* __restrict__ bsum,
                                                int* __restrict__ cur, int N) {
    int gid = blockIdx.x * blockDim.x + threadIdx.x;
    if (gid < N) {
        int o = off[gid] + bsum[gid >> 10];
        off[gid] = o;
        cur[gid] = o;
    }
}

__global__ __launch_bounds__(256) void reorder_adj(const int* __restrict__ src,
                                                   const int* __restrict__ dst,
                                                   const float* __restrict__ val,
                                                   const float* __restrict__ cci,
                                                   const float* __restrict__ a,
                                                   int* __restrict__ cur,
                                                   int2* __restrict__ csr, int E) {
    int e = blockIdx.x * blockDim.x + threadIdx.x;
    if (e >= E) return;
    float c = val[e] * (cci[e * 3 + 0] * a[0] + cci[e * 3 + 1] * a[1] +
                        cci[e * 3 + 2] * a[2]);
    int pos = atomicAdd(&cur[dst[e]], 1);
    csr[pos] = make_int2(src[e], __float_as_int(c));
}

// =====================================================================
// CSR gather-side segment sum (fp16 messages, fp32 accumulate).
// 16 lanes/node, unroll-4 edge loop, single STG.128 per node.
// =====================================================================
__global__ __launch_bounds__(256) void csr_accum(const int* __restrict__ off,
                                                 const int* __restrict__ deg,
                                                 const int2* __restrict__ csr,
                                                 const __half* __restrict__ m,
                                                 float* __restrict__ acc, int N) {
    int tid = threadIdx.x;
    int node = blockIdx.x * 16 + (tid >> 4);
    int sub = tid & 15;
    int start = off[node];
    int d = deg[node];
    float4 s = make_float4(0.f, 0.f, 0.f, 0.f);
    int j = 0;
    for (; j + 4 <= d; j += 4) {
        int2 e0 = csr[start + j];
        int2 e1 = csr[start + j + 1];
        int2 e2 = csr[start + j + 2];
        int2 e3 = csr[start + j + 3];
        float4 v0 = gather_h4(m, e0.x, sub);
        float4 v1 = gather_h4(m, e1.x, sub);
        float4 v2 = gather_h4(m, e2.x, sub);
        float4 v3 = gather_h4(m, e3.x, sub);
        float c0 = __int_as_float(e0.y), c1 = __int_as_float(e1.y);
        float c2 = __int_as_float(e2.y), c3 = __int_as_float(e3.y);
        s.x = fmaf(c0, v0.x, s.x); s.y = fmaf(c0, v0.y, s.y);
        s.z = fmaf(c0, v0.z, s.z); s.w = fmaf(c0, v0.w, s.w);
        s.x = fmaf(c1, v1.x, s.x); s.y = fmaf(c1, v1.y, s.y);
        s.z = fmaf(c1, v1.z, s.z); s.w = fmaf(c1, v1.w, s.w);
        s.x = fmaf(c2, v2.x, s.x); s.y = fmaf(c2, v2.y, s.y);
        s.z = fmaf(c2, v2.z, s.z); s.w = fmaf(c2, v2.w, s.w);
        s.x = fmaf(c3, v3.x, s.x); s.y = fmaf(c3, v3.y, s.y);
        s.z = fmaf(c3, v3.z, s.z); s.w = fmaf(c3, v3.w, s.w);
    }
    for (; j < d; j++) {
        int2 e0 = csr[start + j];
        float4 v0 = gather_h4(m, e0.x, sub);
        float c0 = __int_as_float(e0.y);
        s.x = fmaf(c0, v0.x, s.x); s.y = fmaf(c0, v0.y, s.y);
        s.z = fmaf(c0, v0.z, s.z); s.w = fmaf(c0, v0.w, s.w);
    }
    reinterpret_cast<float4*>(acc + (long)node * 64)[sub] = s;
}

// =====================================================================
// Incidence scatter (fp16 gathers, fp32 RED, ILP-2 x 2 directions).
// =====================================================================
__global__ __launch_bounds__(256) void scatter_inc2(const __half* __restrict__ ms,
                                                    const __half* __restrict__ mt,
                                                    const int* __restrict__ row,
                                                    const int* __restrict__ col,
                                                    const float* __restrict__ val,
                                                    float* __restrict__ accB0,
                                                    float* __restrict__ accB1, int E) {
    int base = blockIdx.x * 32;
    int tid = threadIdx.x;
    int le = tid >> 4, sub = tid & 15;
    int e0 = base + le;
    int e1 = base + 16 + le;

    int r0 = row[e0], r1 = row[e1];
    int c0 = col[e0], c1 = col[e1];
    float v0 = val[e0], v1 = val[e1];

    float4 a0 = gather_h4(ms, c0, sub);
    float4 a1 = gather_h4(ms, c1, sub);
    float4 b0 = gather_h4(mt, r0, sub);
    float4 b1 = gather_h4(mt, r1, sub);

    a0.x *= v0; a0.y *= v0; a0.z *= v0; a0.w *= v0;
    a1.x *= v1; a1.y *= v1; a1.z *= v1; a1.w *= v1;
    b0.x *= v0; b0.y *= v0; b0.z *= v0; b0.w *= v0;
    b1.x *= v1; b1.y *= v1; b1.z *= v1; b1.w *= v1;

    float* pa0 = accB0 + (long)r0 * 64 + sub * 4;
    float* pa1 = accB0 + (long)r1 * 64 + sub * 4;
    float* pb0 = accB1 + (long)c0 * 64 + sub * 4;
    float* pb1 = accB1 + (long)c1 * 64 + sub * 4;
    asm volatile("red.global.add.v4.f32 [%0], {%1,%2,%3,%4};"
                 :: "l"(pa0), "f"(a0.x), "f"(a0.y), "f"(a0.z), "f"(a0.w) : "memory");
    asm volatile("red.global.add.v4.f32 [%0], {%1,%2,%3,%4};"
                 :: "l"(pa1), "f"(a1.x), "f"(a1.y), "f"(a1.z), "f"(a1.w) : "memory");
    asm volatile("red.global.add.v4.f32 [%0], {%1,%2,%3,%4};"
                 :: "l"(pb0), "f"(b0.x), "f"(b0.y), "f"(b0.z), "f"(b0.w) : "memory");
    asm volatile("red.global.add.v4.f32 [%0], {%1,%2,%3,%4};"
                 :: "l"(pb1), "f"(b1.x), "f"(b1.y), "f"(b1.z), "f"(b1.w) : "memory");
}

// ---------------- stream/event pool: LAZY init, 3 streams ----------------
static cudaStream_t s1 = 0, s2 = 0, s3 = 0;
static cudaEvent_t eRoot = 0, eB1 = 0, eG0 = 0, eG1 = 0, eI = 0, eF0 = 0;
static int g_init_state = 0;

static void ensure_init() {
    if (g_init_state != 0) return;
    bool ok = true;
    ok &= (cudaStreamCreateWithFlags(&s1, cudaStreamNonBlocking) == cudaSuccess);
    ok &= (cudaStreamCreateWithFlags(&s2, cudaStreamNonBlocking) == cudaSuccess);
    ok &= (cudaStreamCreateWithFlags(&s3, cudaStreamNonBlocking) == cudaSuccess);
    ok &= (cudaEventCreateWithFlags(&eRoot, cudaEventDisableTiming) == cudaSuccess);
    ok &= (cudaEventCreateWithFlags(&eB1, cudaEventDisableTiming) == cudaSuccess);
    ok &= (cudaEventCreateWithFlags(&eG0, cudaEventDisableTiming) == cudaSuccess);
    ok &= (cudaEventCreateWithFlags(&eG1, cudaEventDisableTiming) == cudaSuccess);
    ok &= (cudaEventCreateWithFlags(&eI, cudaEventDisableTiming) == cudaSuccess);
    ok &= (cudaEventCreateWithFlags(&eF0, cudaEventDisableTiming) == cudaSuccess);
    g_init_state = ok ? 1 : -1;
}

// ---------------- launch ----------------
extern "C" void kernel_launch(void* const* d_in, const int* in_sizes, int n_in,
                              void* d_out, int out_size) {
    ensure_init();

    const float* x0   = (const float*)d_in[0];
    const float* x1   = (const float*)d_in[1];
    const float* x2   = (const float*)d_in[2];
    const float* x3   = (const float*)d_in[3];
    const float* x4   = (const float*)d_in[4];
    const int*   adj0 = (const int*)d_in[5];
    const float* adj0v= (const float*)d_in[6];
    const int*   adj1 = (const int*)d_in[7];
    const float* adj1v= (const float*)d_in[8];
    const int*   inc  = (const int*)d_in[9];
    const float* incv = (const float*)d_in[10];
    const float* cci0 = (const float*)d_in[11];
    const float* cci1 = (const float*)d_in[12];
    const float* Whbs0= (const float*)d_in[13];
    const float* ahbs0= (const float*)d_in[14];
    const float* Whbs1= (const float*)d_in[15];
    const float* ahbs1= (const float*)d_in[16];
    const float* Ws   = (const float*)d_in[17];
    const float* Wt   = (const float*)d_in[18];
    const float* Wag0 = (const float*)d_in[19];
    const float* Wag1 = (const float*)d_in[20];
    float* out = (float*)d_out;

    __half *pm0, *pm1, *pms, *pmt;
    float *pA0, *pB0, *pA1, *pB1;
    int *pdeg0, *poff0, *pcur0, *pdeg1, *poff1, *pcur1, *pbs0, *pbs1;
    int2 *pcsr0, *pcsr1;
    cudaGetSymbolAddress((void**)&pm0, g_m0);
    cudaGetSymbolAddress((void**)&pm1, g_m1);
    cudaGetSymbolAddress((void**)&pms, g_ms);
    cudaGetSymbolAddress((void**)&pmt, g_mt);
    cudaGetSymbolAddress((void**)&pA0, g_accA0);
    cudaGetSymbolAddress((void**)&pB0, g_accB0);
    cudaGetSymbolAddress((void**)&pA1, g_accA1);
    cudaGetSymbolAddress((void**)&pB1, g_accB1);
    cudaGetSymbolAddress((void**)&pdeg0, g_deg0);
    cudaGetSymbolAddress((void**)&poff0, g_off0);
    cudaGetSymbolAddress((void**)&pcur0, g_cur0);
    cudaGetSymbolAddress((void**)&pdeg1, g_deg1);
    cudaGetSymbolAddress((void**)&poff1, g_off1);
    cudaGetSymbolAddress((void**)&pcur1, g_cur1);
    cudaGetSymbolAddress((void**)&pbs0, g_bsum0);
    cudaGetSymbolAddress((void**)&pbs1, g_bsum1);
    cudaGetSymbolAddress((void**)&pcsr0, g_csr0);
    cudaGetSymbolAddress((void**)&pcsr1, g_csr1);

    const int nb1 = (CN1 + 1023) / 1024;   // 147
    const int nb0 = (CN0 + 1023) / 1024;   // 49

    if (g_init_state == 1) {
        // ---- fork ----
        cudaEventRecord(eRoot, 0);
        cudaStreamWaitEvent(s1, eRoot, 0);
        cudaStreamWaitEvent(s2, eRoot, 0);
        cudaStreamWaitEvent(s3, eRoot, 0);

        // s2: CSR build for E1 (critical: feeds csr_accum1 on main)
        cudaMemsetAsync(pdeg1, 0, sizeof(int) * CN1, s2);
        hist_kernel<<<(CE1 + 255) / 256, 256, 0, s2>>>(adj1 + CE1, pdeg1, CE1);
        scan_block<<<nb1, 1024, 0, s2>>>(pdeg1, poff1, pbs1, CN1);
        scan_top<<<1, 256, 0, s2>>>(pbs1, nb1);
        scan_add<<<(CN1 + 255) / 256, 256, 0, s2>>>(poff1, pbs1, pcur1, CN1);
        reorder_adj<<<(CE1 + 255) / 256, 256, 0, s2>>>(adj1, adj1 + CE1, adj1v, cci1,
                                                       ahbs1, pcur1, pcsr1, CE1);
        cudaEventRecord(eB1, s2);

        // s1: chain0 entirely in-stream — build0, gemm0, csr_accum0, fused0
        cudaMemsetAsync(pdeg0, 0, sizeof(int) * CN0, s1);
        hist_kernel<<<(CE0 + 255) / 256, 256, 0, s1>>>(adj0 + CE0, pdeg0, CE0);
        scan_block<<<nb0, 1024, 0, s1>>>(pdeg0, poff0, pbs0, CN0);
        scan_top<<<1, 256, 0, s1>>>(pbs0, nb0);
        scan_add<<<(CN0 + 255) / 256, 256, 0, s1>>>(poff0, pbs0, pcur0, CN0);
        reorder_adj<<<(CE0 + 255) / 256, 256, 0, s1>>>(adj0, adj0 + CE0, adj0v, cci0,
                                                       ahbs0, pcur0, pcsr0, CE0);
        gemm64_dual<<<(CN0 + 127) / 128, 256, 0, s1>>>(x0, Whbs0, Wt, pm0, pmt, CN0);
        cudaEventRecord(eG0, s1);
        csr_accum<<<CN0 / 16, 256, 0, s1>>>(poff0, pdeg0, pcsr0, pm0, pA0, CN0);

        // main: chain1 — gemm(x1)
        gemm64_dual<<<(CN1 + 127) / 128, 256, 0, 0>>>(x1, Whbs1, Ws, pm1, pms, CN1);
        cudaEventRecord(eG1, 0);

        // s3: memset B accumulators + pass-through copies, then incidence scatter
        cudaMemsetAsync(pB0, 0, sizeof(float) * (size_t)CN0 * DD, s3);
        cudaMemsetAsync(pB1, 0, sizeof(float) * (size_t)CN1 * DD, s3);
        cudaMemcpyAsync(out + (long)(CN0 + CN1) * DD, x2, sizeof(float) * (size_t)CN2 * DD,
                        cudaMemcpyDeviceToDevice, s3);
        cudaMemcpyAsync(out + (long)(CN0 + CN1 + CN2) * DD, x3, sizeof(float) * (size_t)CN3 * DD,
                        cudaMemcpyDeviceToDevice, s3);
        cudaMemcpyAsync(out + (long)(CN0 + CN1 + CN2 + CN3) * DD, x4,
                        sizeof(float) * (size_t)CN4 * DD, cudaMemcpyDeviceToDevice, s3);
        cudaStreamWaitEvent(s3, eG0, 0);
        cudaStreamWaitEvent(s3, eG1, 0);
        scatter_inc2<<<CNNZ / 32, 256, 0, s3>>>(pms, pmt, inc, inc + CNNZ, incv,
                                                pB0, pB1, CNNZ);
        cudaEventRecord(eI, s3);

        // s1: fused0 after incidence scatter
        cudaStreamWaitEvent(s1, eI, 0);
        gemm64_fused<<<(CN0 + 127) / 128, 256, 0, s1>>>(pA0, pB0, Wag0, out, CN0);
        cudaEventRecord(eF0, s1);

        // main: csr_accum1 then fused1, join
        cudaStreamWaitEvent(0, eB1, 0);
        csr_accum<<<CN1 / 16, 256, 0, 0>>>(poff1, pdeg1, pcsr1, pm1, pA1, CN1);
        cudaStreamWaitEvent(0, eI, 0);
        gemm64_fused<<<(CN1 + 127) / 128, 256, 0, 0>>>(pA1, pB1, Wag1,
                                                       out + (long)CN0 * DD, CN1);
        cudaStreamWaitEvent(0, eF0, 0);  // joins s1 (s2 via eB1, s3 via eI)
    } else {
        // ======== serial fallback ========
        cudaMemsetAsync(pB0, 0, sizeof(float) * (size_t)CN0 * DD);
        cudaMemsetAsync(pB1, 0, sizeof(float) * (size_t)CN1 * DD);
        cudaMemsetAsync(pdeg1, 0, sizeof(int) * CN1);
        hist_kernel<<<(CE1 + 255) / 256, 256>>>(adj1 + CE1, pdeg1, CE1);
        scan_block<<<nb1, 1024>>>(pdeg1, poff1, pbs1, CN1);
        scan_top<<<1, 256>>>(pbs1, nb1);
        scan_add<<<(CN1 + 255) / 256, 256>>>(poff1, pbs1, pcur1, CN1);
        reorder_adj<<<(CE1 + 255) / 256, 256>>>(adj1, adj1 + CE1, adj1v, cci1,
                                                ahbs1, pcur1, pcsr1, CE1);
        cudaMemsetAsync(pdeg0, 0, sizeof(int) * CN0);
        hist_kernel<<<(CE0 + 255) / 256, 256>>>(adj0 + CE0, pdeg0, CE0);
        scan_block<<<nb0, 1024>>>(pdeg0, poff0, pbs0, CN0);
        scan_top<<<1, 256>>>(pbs0, nb0);
        scan_add<<<(CN0 + 255) / 256, 256>>>(poff0, pbs0, pcur0, CN0);
        reorder_adj<<<(CE0 + 255) / 256, 256>>>(adj0, adj0 + CE0, adj0v, cci0,
                                                ahbs0, pcur0, pcsr0, CE0);
        gemm64_dual<<<(CN0 + 127) / 128, 256>>>(x0, Whbs0, Wt, pm0, pmt, CN0);
        gemm64_dual<<<(CN1 + 127) / 128, 256>>>(x1, Whbs1, Ws, pm1, pms, CN1);
        csr_accum<<<CN0 / 16, 256>>>(poff0, pdeg0, pcsr0, pm0, pA0, CN0);
        csr_accum<<<CN1 / 16, 256>>>(poff1, pdeg1, pcsr1, pm1, pA1, CN1);
        scatter_inc2<<<CNNZ / 32, 256>>>(pms, pmt, inc, inc + CNNZ, incv, pB0, pB1, CNNZ);
        gemm64_fused<<<(CN0 + 127) / 128, 256>>>(pA0, pB0, Wag0, out, CN0);
        gemm64_fused<<<(CN1 + 127) / 128, 256>>>(pA1, pB1, Wag1, out + (long)CN0 * DD, CN1);
        cudaMemcpyAsync(out + (long)(CN0 + CN1) * DD, x2, sizeof(float) * (size_t)CN2 * DD,
                        cudaMemcpyDeviceToDevice);
        cudaMemcpyAsync(out + (long)(CN0 + CN1 + CN2) * DD, x3, sizeof(float) * (size_t)CN3 * DD,
                        cudaMemcpyDeviceToDevice);
        cudaMemcpyAsync(out + (long)(CN0 + CN1 + CN2 + CN3) * DD, x4,
                        sizeof(float) * (size_t)CN4 * DD, cudaMemcpyDeviceToDevice);
    }
}